// round 8
// baseline (speedup 1.0000x reference)
#include <cuda_runtime.h>
#include <cuda_bf16.h>
#include <math.h>
#include <stdint.h>

// Problem constants
#define Bsz 2
#define Hh  64
#define Ww  24
#define Cc  256
#define Pp  8
#define HP  8
#define NHh 8
#define DK  32
#define KV  4
#define NROW (Bsz*Hh*Ww)       // 3072
#define NELEM (NROW*Cc)        // 786432
#define LBLK (HP*Ww)           // 192
#define LKEY (KV*LBLK)         // 768
#define KTOT (25*Cc)           // 6400 conv K
#define NSPLIT 3
#define NCH16 400              // 6400 / 16
#define WSZ ((long)Cc*Cc)

#define QK_SCALE (0.17677669529663687f * 1.44269504088896340f)

// ---------------- device scratch ----------------
__device__ float g_buf[12u * NELEM];
__device__ float g_loc[2 * 16 * Cc];
__device__ float g_bsum[Cc];
__device__ int   g_R[Bsz * Pp * KV];
__device__ __nv_bfloat16 g_x_hi[NELEM],   g_x_lo[NELEM];
__device__ __nv_bfloat16 g_act_hi[3u*NELEM], g_act_lo[3u*NELEM];
__device__ __nv_bfloat16 g_ctx_hi[NELEM], g_ctx_lo[NELEM];
__device__ __nv_bfloat16 g_kvg_hi[NELEM], g_kvg_lo[NELEM];
__device__ __nv_bfloat16 g_wt_hi[Cc * KTOT], g_wt_lo[Cc * KTOT];
__device__ __nv_bfloat16 g_w8_hi[8u*Cc*Cc], g_w8_lo[8u*Cc*Cc];

// ---------------- packed f32x2 helpers ----------------
__device__ __forceinline__ unsigned long long pk2(float lo, float hi) {
    unsigned long long r;
    asm("mov.b64 %0, {%1, %2};" : "=l"(r)
        : "r"(__float_as_uint(lo)), "r"(__float_as_uint(hi)));
    return r;
}
__device__ __forceinline__ unsigned long long ffma2(unsigned long long a,
                                                    unsigned long long b,
                                                    unsigned long long c) {
    unsigned long long d;
    asm("fma.rn.f32x2 %0, %1, %2, %3;" : "=l"(d) : "l"(a), "l"(b), "l"(c));
    return d;
}
__device__ __forceinline__ unsigned long long fmul2(unsigned long long a,
                                                    unsigned long long b) {
    unsigned long long d;
    asm("mul.rn.f32x2 %0, %1, %2;" : "=l"(d) : "l"(a), "l"(b));
    return d;
}
__device__ __forceinline__ float2 upk2(unsigned long long v) {
    unsigned int lo, hi;
    asm("mov.b64 {%0, %1}, %2;" : "=r"(lo), "=r"(hi) : "l"(v));
    return make_float2(__uint_as_float(lo), __uint_as_float(hi));
}
__device__ __forceinline__ float ex2f(float x) {
    float r;
    asm("ex2.approx.ftz.f32 %0, %1;" : "=f"(r) : "f"(x));
    return r;
}

// ---------------- warp MMA / pipeline helpers ----------------
__device__ __forceinline__ uint32_t smem_u32(const void* p) {
    uint32_t a;
    asm("{ .reg .u64 t; cvta.to.shared.u64 t, %1; cvt.u32.u64 %0, t; }"
        : "=r"(a) : "l"(p));
    return a;
}
// 32B-row swizzle: XOR unit bit (bit4) with row bit2 (bit7)
#define SWZ32(o) ((o) ^ (((o) >> 3) & 0x10))
#define STAGE 16384

#define CP16(dst, src) asm volatile("cp.async.cg.shared.global [%0], [%1], 16;" :: "r"(dst), "l"(src))
#define CPC()  asm volatile("cp.async.commit_group;" ::: "memory")
#define CPW1() asm volatile("cp.async.wait_group 1;" ::: "memory")

__device__ __forceinline__ void ldsm4(uint32_t* r, uint32_t addr) {
    asm volatile("ldmatrix.sync.aligned.m8n8.x4.shared.b16 {%0,%1,%2,%3}, [%4];"
                 : "=r"(r[0]), "=r"(r[1]), "=r"(r[2]), "=r"(r[3]) : "r"(addr));
}
__device__ __forceinline__ void mma_bf16(float* c, const uint32_t* a, const uint32_t* b) {
    asm volatile(
        "mma.sync.aligned.m16n8k16.row.col.f32.bf16.bf16.f32 "
        "{%0,%1,%2,%3}, {%4,%5,%6,%7}, {%8,%9}, {%0,%1,%2,%3};"
        : "+f"(c[0]), "+f"(c[1]), "+f"(c[2]), "+f"(c[3])
        : "r"(a[0]), "r"(a[1]), "r"(a[2]), "r"(a[3]), "r"(b[0]), "r"(b[1]));
}

// compute one K=16 chunk from stage st (shared by gemm & conv; tile 128x128, warp 32x64)
__device__ __forceinline__ void compute_chunk(uint32_t sb, int st, int wm, int wn, int lane,
                                              float acc[2][8][4])
{
    const uint32_t base = sb + st * STAGE;
    const int tile = lane >> 3;
    uint32_t ahi[2][4], alo[2][4];
#pragma unroll
    for (int mh = 0; mh < 2; mh++) {
        const int row = wm * 32 + mh * 16 + ((tile & 1) << 3) + (lane & 7);
        const int unit = tile >> 1;
        const uint32_t so = SWZ32((uint32_t)(row * 32 + unit * 16));
        ldsm4(ahi[mh], base + so);
        ldsm4(alo[mh], base + 4096 + so);
    }
    uint32_t bhi[8][2], blo[8][2];
#pragma unroll
    for (int ng = 0; ng < 4; ng++) {
        const int row = wn * 64 + ng * 16 + ((tile >> 1) << 3) + (lane & 7);
        const int unit = tile & 1;
        const uint32_t so = SWZ32((uint32_t)(row * 32 + unit * 16));
        uint32_t th[4], tl[4];
        ldsm4(th, base + 8192 + so);
        ldsm4(tl, base + 12288 + so);
        bhi[ng * 2][0] = th[0]; bhi[ng * 2][1] = th[1];
        bhi[ng * 2 + 1][0] = th[2]; bhi[ng * 2 + 1][1] = th[3];
        blo[ng * 2][0] = tl[0]; blo[ng * 2][1] = tl[1];
        blo[ng * 2 + 1][0] = tl[2]; blo[ng * 2 + 1][1] = tl[3];
    }
#pragma unroll
    for (int mh = 0; mh < 2; mh++)
#pragma unroll
        for (int nt = 0; nt < 8; nt++) {
            mma_bf16(acc[mh][nt], ahi[mh], bhi[nt]);
            mma_bf16(acc[mh][nt], alo[mh], bhi[nt]);
            mma_bf16(acc[mh][nt], ahi[mh], blo[nt]);
        }
}

// ================= tensor-core GEMM, 128x128 tile, cp.async 3-stage =================
struct GemmSetT {
    const __nv_bfloat16 *Ah[4], *Al[4], *Bh[4], *Bl[4];
    const float* bias[4];
    float* C[4];
    __nv_bfloat16 *Ch[4], *Cl[4];
};

__global__ __launch_bounds__(256, 1)
void gemm_mma_kernel(GemmSetT gs)
{
    __shared__ char smem[3 * STAGE];
    const uint32_t sb = smem_u32(smem);

    const int z = blockIdx.z;
    const __nv_bfloat16* __restrict__ Ah = gs.Ah[z];
    const __nv_bfloat16* __restrict__ Al = gs.Al[z];
    const __nv_bfloat16* __restrict__ Bh = gs.Bh[z];
    const __nv_bfloat16* __restrict__ Bl = gs.Bl[z];
    const float* __restrict__ bias = gs.bias[z];
    float* __restrict__ C = gs.C[z];
    __nv_bfloat16* __restrict__ Ch = gs.Ch[z];
    __nv_bfloat16* __restrict__ Cl = gs.Cl[z];

    const int tid  = threadIdx.x;
    const int wid  = tid >> 5;
    const int lane = tid & 31;
    const int m0 = blockIdx.x * 128;
    const int n0 = blockIdx.y * 128;
    const int wm = wid & 3;
    const int wn = wid >> 2;

    const int l_row = tid >> 1;       // 0..127
    const int l_seg = tid & 1;        // 0..1
    const uint32_t so = SWZ32((uint32_t)(l_row * 32 + l_seg * 16));
    const long aRow = (long)(m0 + l_row) * Cc + l_seg * 8;
    const long bRow = (long)(n0 + l_row) * Cc + l_seg * 8;

    float acc[2][8][4];
#pragma unroll
    for (int i = 0; i < 2; i++)
#pragma unroll
        for (int j = 0; j < 8; j++)
#pragma unroll
            for (int q = 0; q < 4; q++) acc[i][j][q] = 0.f;

    // prologue: issue chunks 0,1
#pragma unroll
    for (int pc = 0; pc < 2; pc++) {
        const uint32_t dst = sb + pc * STAGE + so;
        const int kb = pc * 16;
        CP16(dst,         (const char*)(Ah + aRow + kb));
        CP16(dst + 4096,  (const char*)(Al + aRow + kb));
        CP16(dst + 8192,  (const char*)(Bh + bRow + kb));
        CP16(dst + 12288, (const char*)(Bl + bRow + kb));
        CPC();
    }

    int st = 0;
    for (int c = 0; c < 16; c++) {
        CPW1();
        __syncthreads();
        // issue chunk c+2 (empty commit keeps group accounting uniform)
        if (c + 2 < 16) {
            const int s2 = (st + 2 >= 3) ? st - 1 : st + 2;
            const uint32_t dst = sb + s2 * STAGE + so;
            const int kb = (c + 2) * 16;
            CP16(dst,         (const char*)(Ah + aRow + kb));
            CP16(dst + 4096,  (const char*)(Al + aRow + kb));
            CP16(dst + 8192,  (const char*)(Bh + bRow + kb));
            CP16(dst + 12288, (const char*)(Bl + bRow + kb));
        }
        CPC();
        compute_chunk(sb, st, wm, wn, lane, acc);
        st = (st + 1 == 3) ? 0 : st + 1;
    }

    // epilogue
#pragma unroll
    for (int mh = 0; mh < 2; mh++) {
        const int mrow = m0 + wm * 32 + mh * 16 + (lane >> 2);
#pragma unroll
        for (int nt = 0; nt < 8; nt++) {
            const int n = n0 + wn * 64 + nt * 8 + (lane & 3) * 2;
            const float2 bi = *(const float2*)&bias[n];
            const float v0 = acc[mh][nt][0] + bi.x;
            const float v1 = acc[mh][nt][1] + bi.y;
            const float v2 = acc[mh][nt][2] + bi.x;
            const float v3 = acc[mh][nt][3] + bi.y;
            const size_t o0 = (size_t)mrow * Cc + n;
            const size_t o1 = (size_t)(mrow + 8) * Cc + n;
            *(float2*)&C[o0] = make_float2(v0, v1);
            *(float2*)&C[o1] = make_float2(v2, v3);
            if (Ch) {
                const __nv_bfloat16 h0 = __float2bfloat16(v0);
                const __nv_bfloat16 h1 = __float2bfloat16(v1);
                const __nv_bfloat16 h2 = __float2bfloat16(v2);
                const __nv_bfloat16 h3 = __float2bfloat16(v3);
                *(__nv_bfloat162*)&Ch[o0] = __nv_bfloat162(h0, h1);
                *(__nv_bfloat162*)&Ch[o1] = __nv_bfloat162(h2, h3);
                *(__nv_bfloat162*)&Cl[o0] = __nv_bfloat162(
                    __float2bfloat16(v0 - __bfloat162float(h0)),
                    __float2bfloat16(v1 - __bfloat162float(h1)));
                *(__nv_bfloat162*)&Cl[o1] = __nv_bfloat162(
                    __float2bfloat16(v2 - __bfloat162float(h2)),
                    __float2bfloat16(v3 - __bfloat162float(h3)));
            }
        }
    }
}

// ---------------- conv implicit GEMM, 128x128 tile, cp.async 3-stage ----------------
__global__ __launch_bounds__(256, 1)
void conv_mma_kernel(const __nv_bfloat16* __restrict__ a_hi,
                     const __nv_bfloat16* __restrict__ a_lo,
                     const __nv_bfloat16* __restrict__ b_hi,
                     const __nv_bfloat16* __restrict__ b_lo,
                     float* __restrict__ part)
{
    __shared__ char smem[3 * STAGE];
    const uint32_t sb = smem_u32(smem);

    const int tid  = threadIdx.x;
    const int wid  = tid >> 5;
    const int lane = tid & 31;
    const int m0 = blockIdx.x * 128;
    const int n0 = blockIdx.y * 128;
    const int z  = blockIdx.z;
    const int cbeg = (z * NCH16) / 3;
    const int cend = ((z + 1) * NCH16) / 3;

    const int wm = wid & 3;
    const int wn = wid >> 2;

    const int l_row = tid >> 1;
    const int l_seg = tid & 1;
    const uint32_t so = SWZ32((uint32_t)(l_row * 32 + l_seg * 16));
    const int am = m0 + l_row;
    const int a_b = am / (Hh * Ww);
    const int a_h = (am / Ww) % Hh;
    const int a_w = am % Ww;
    const long a_base = (long)a_b * Hh * Ww * Cc;
    const long bRow = (long)(n0 + l_row) * KTOT + l_seg * 8;

    float acc[2][8][4];
#pragma unroll
    for (int i = 0; i < 2; i++)
#pragma unroll
        for (int j = 0; j < 8; j++)
#pragma unroll
            for (int q = 0; q < 4; q++) acc[i][j][q] = 0.f;

    // issuer lambda behavior (manually expanded): chunk c -> stage s
    // A: oob rows get STS zeros (visible after the same barrier)
#define CONV_ISSUE(cc, ss)                                                     \
    {                                                                          \
        const int kb = (cc) * 16;                                              \
        const int patch = kb >> 8;                                             \
        const int kh = patch / 5, kw = patch % 5;                              \
        const int ci0 = kb & 255;                                              \
        const int hh = a_h + kh - 2;                                           \
        const int ww = a_w + kw - 2;                                           \
        const uint32_t dst = sb + (ss) * STAGE + so;                           \
        if (hh >= 0 && hh < Hh && ww >= 0 && ww < Ww) {                        \
            const long off = a_base + ((long)hh * Ww + ww) * Cc + ci0 + l_seg * 8; \
            CP16(dst,        (const char*)(a_hi + off));                       \
            CP16(dst + 4096, (const char*)(a_lo + off));                       \
        } else {                                                               \
            *(uint4*)(smem + (ss) * STAGE + so)        = make_uint4(0,0,0,0);  \
            *(uint4*)(smem + (ss) * STAGE + so + 4096) = make_uint4(0,0,0,0);  \
        }                                                                      \
        CP16(dst + 8192,  (const char*)(b_hi + bRow + kb));                    \
        CP16(dst + 12288, (const char*)(b_lo + bRow + kb));                    \
    }

    CONV_ISSUE(cbeg, 0); CPC();
    if (cbeg + 1 < cend) CONV_ISSUE(cbeg + 1, 1);
    CPC();

    int st = 0;
    for (int c = cbeg; c < cend; c++) {
        CPW1();
        __syncthreads();
        if (c + 2 < cend) {
            const int s2 = (st + 2 >= 3) ? st - 1 : st + 2;
            CONV_ISSUE(c + 2, s2);
        }
        CPC();
        compute_chunk(sb, st, wm, wn, lane, acc);
        st = (st + 1 == 3) ? 0 : st + 1;
    }
#undef CONV_ISSUE

    float* base = part + (size_t)z * NELEM;
#pragma unroll
    for (int mh = 0; mh < 2; mh++) {
        const int mrow = m0 + wm * 32 + mh * 16 + (lane >> 2);
#pragma unroll
        for (int nt = 0; nt < 8; nt++) {
            const int n = n0 + wn * 64 + nt * 8 + (lane & 3) * 2;
            *(float2*)&base[(size_t)mrow * Cc + n] =
                make_float2(acc[mh][nt][0], acc[mh][nt][1]);
            *(float2*)&base[(size_t)(mrow + 8) * Cc + n] =
                make_float2(acc[mh][nt][2], acc[mh][nt][3]);
        }
    }
}

// ---------------- fused decompose: 8 proj weights + conv weight + x ----------------
struct DecompAll {
    const float *w[7];
    const float *wk, *wv;
    const float *convw;
    const float *x;
    const float *bk, *bv;
};

__global__ void decomp_all_kernel(DecompAll da)
{
    const int z = blockIdx.z;
    const int bx = blockIdx.x, by = blockIdx.y;
    const int tid = threadIdx.x;
    const int tx = tid & 31, ty = tid >> 5;

    if (z <= 7) {
        if (bx >= 8) return;
        if (z == 7 && bx == 0 && by == 0)
            g_bsum[tid] = da.bk[tid] + da.bv[tid];
        __shared__ float tile[32][33];
        const int k0 = bx * 32, n0 = by * 32;
#pragma unroll
        for (int i = 0; i < 4; i++) {
            const long off = (long)(k0 + ty + i * 8) * Cc + n0 + tx;
            tile[ty + i * 8][tx] = (z < 7) ? da.w[z][off] : (da.wk[off] + da.wv[off]);
        }
        __syncthreads();
#pragma unroll
        for (int i = 0; i < 4; i++) {
            const float v = tile[tx][ty + i * 8];
            const __nv_bfloat16 h = __float2bfloat16(v);
            const long o = (long)z * WSZ + (long)(n0 + ty + i * 8) * Cc + k0 + tx;
            g_w8_hi[o] = h;
            g_w8_lo[o] = __float2bfloat16(v - __bfloat162float(h));
        }
    } else if (z == 8) {
        __shared__ float tile[32][33];
        const int k0 = bx * 32, n0 = by * 32;
#pragma unroll
        for (int i = 0; i < 4; i++)
            tile[ty + i * 8][tx] = da.convw[(long)(k0 + ty + i * 8) * Cc + n0 + tx];
        __syncthreads();
#pragma unroll
        for (int i = 0; i < 4; i++) {
            const float v = tile[tx][ty + i * 8];
            const __nv_bfloat16 h = __float2bfloat16(v);
            const long o = (long)(n0 + ty + i * 8) * KTOT + k0 + tx;
            g_wt_hi[o] = h;
            g_wt_lo[o] = __float2bfloat16(v - __bfloat162float(h));
        }
    } else {
        const int idx = (by * 200 + bx) * 256 + tid;
        if (idx < NELEM / 4) {
            const float4 v = ((const float4*)da.x)[idx];
            __nv_bfloat16 h0 = __float2bfloat16(v.x), h1 = __float2bfloat16(v.y);
            __nv_bfloat16 h2 = __float2bfloat16(v.z), h3 = __float2bfloat16(v.w);
            ((__nv_bfloat162*)g_x_hi)[idx * 2]     = __nv_bfloat162(h0, h1);
            ((__nv_bfloat162*)g_x_hi)[idx * 2 + 1] = __nv_bfloat162(h2, h3);
            ((__nv_bfloat162*)g_x_lo)[idx * 2]     = __nv_bfloat162(
                __float2bfloat16(v.x - __bfloat162float(h0)),
                __float2bfloat16(v.y - __bfloat162float(h1)));
            ((__nv_bfloat162*)g_x_lo)[idx * 2 + 1] = __nv_bfloat162(
                __float2bfloat16(v.z - __bfloat162float(h2)),
                __float2bfloat16(v.w - __bfloat162float(h3)));
        }
    }
}

// ---------------- block mean pooling ----------------
__global__ void pool_kernel(const float* __restrict__ qp, const float* __restrict__ kp,
                            float* __restrict__ qloc, float* __restrict__ kloc)
{
    const int bp = blockIdx.x;
    const int c  = threadIdx.x;
    const float* qb = qp + (long)bp * LBLK * Cc + c;
    const float* kb = kp + (long)bp * LBLK * Cc + c;
    float sq = 0.f, sk = 0.f;
    for (int i = 0; i < LBLK; i++) { sq += qb[i * Cc]; sk += kb[i * Cc]; }
    qloc[bp * Cc + c] = sq * (1.f / (float)LBLK);
    kloc[bp * Cc + c] = sk * (1.f / (float)LBLK);
}

// ---------------- routing ----------------
__global__ void route_kernel(const float* __restrict__ qloc, const float* __restrict__ kloc,
                             int* __restrict__ R)
{
    const int bp = blockIdx.x;
    const int b  = bp / Pp;
    const int warp = threadIdx.x >> 5;
    const int lane = threadIdx.x & 31;
    __shared__ float s[8];
    const float* q = qloc + bp * Cc;
    const float* k = kloc + (b * Pp + warp) * Cc;
    float partial = 0.f;
    for (int c = lane; c < Cc; c += 32) partial += q[c] * k[c];
#pragma unroll
    for (int o = 16; o; o >>= 1) partial += __shfl_xor_sync(0xffffffff, partial, o);
    if (lane == 0) s[warp] = partial;
    __syncthreads();
    if (threadIdx.x == 0) {
        bool used[8] = {};
        for (int t = 0; t < KV; t++) {
            int best = 0; float bv = -1e30f;
            for (int j = 0; j < Pp; j++)
                if (!used[j] && s[j] > bv) { bv = s[j]; best = j; }
            used[best] = true;
            R[bp * KV + t] = best;
        }
    }
}

// ---------------- attention (MUFU ex2, writes ctx hi/lo) ----------------
#define KCHUNK 128
__global__ void attention_kernel(const float* __restrict__ q2,
                                 const float* __restrict__ k2,
                                 const float* __restrict__ v2,
                                 const int* __restrict__ R,
                                 __nv_bfloat16* __restrict__ ctx_hi,
                                 __nv_bfloat16* __restrict__ ctx_lo)
{
    __shared__ float Ks[KCHUNK * DK];
    __shared__ float Vs[KCHUNK * DK];
    __shared__ int   Rs[KV];

    const int blk = blockIdx.x;
    const int h = blk % NHh;
    const int p = (blk / NHh) % Pp;
    const int b = blk / (NHh * Pp);
    const int tid = threadIdx.x;

    if (tid < KV) Rs[tid] = R[(b * Pp + p) * KV + tid];

    const bool active = (tid < LBLK);
    unsigned long long qv2[DK / 2], acc2[DK / 2];
    float m = -1e30f, l = 0.f;
    if (active) {
        const float* qrow = q2 + ((long)((b * Pp + p) * LBLK + tid)) * Cc + h * DK;
#pragma unroll
        for (int d2 = 0; d2 < DK / 2; d2++) {
            qv2[d2] = pk2(qrow[2 * d2] * QK_SCALE, qrow[2 * d2 + 1] * QK_SCALE);
            acc2[d2] = 0ull;
        }
    }

    for (int ch = 0; ch < LKEY / KCHUNK; ch++) {
        __syncthreads();
        const int kg0 = ch * KCHUNK;
        for (int i = tid; i < KCHUNK * (DK / 4); i += blockDim.x) {
            const int row = i >> 3;
            const int d4  = (i & 7) * 4;
            const int kg  = kg0 + row;
            const int ks  = kg / LBLK;
            const int rr  = kg - ks * LBLK;
            const int r   = Rs[ks];
            const long base = ((long)(b * Pp + r) * LBLK + rr) * Cc + h * DK + d4;
            *(float4*)&Ks[row * DK + d4] = *(const float4*)&k2[base];
            *(float4*)&Vs[row * DK + d4] = *(const float4*)&v2[base];
        }
        __syncthreads();
        if (active) {
            for (int k = 0; k < KCHUNK; k++) {
                const unsigned long long* kr = (const unsigned long long*)&Ks[k * DK];
                unsigned long long s0 = 0ull, s1 = 0ull, s2 = 0ull, s3 = 0ull;
#pragma unroll
                for (int d2 = 0; d2 < DK / 2; d2 += 4) {
                    s0 = ffma2(qv2[d2 + 0], kr[d2 + 0], s0);
                    s1 = ffma2(qv2[d2 + 1], kr[d2 + 1], s1);
                    s2 = ffma2(qv2[d2 + 2], kr[d2 + 2], s2);
                    s3 = ffma2(qv2[d2 + 3], kr[d2 + 3], s3);
                }
                const float2 f0 = upk2(s0), f1 = upk2(s1), f2 = upk2(s2), f3 = upk2(s3);
                const float s = ((f0.x + f0.y) + (f1.x + f1.y)) + ((f2.x + f2.y) + (f3.x + f3.y));
                const float mnew = fmaxf(m, s);
                const float corr = ex2f(m - mnew);
                const float pe   = ex2f(s - mnew);
                l = fmaf(l, corr, pe);
                const unsigned long long cc = pk2(corr, corr);
                const unsigned long long pp = pk2(pe, pe);
                const unsigned long long* vr = (const unsigned long long*)&Vs[k * DK];
#pragma unroll
                for (int d2 = 0; d2 < DK / 2; d2++)
                    acc2[d2] = ffma2(acc2[d2], cc, fmul2(pp, vr[d2]));
                m = mnew;
            }
        }
    }

    if (active) {
        const float inv = 1.0f / l;
        const long base = ((long)((b * Pp + p) * LBLK + tid)) * Cc + h * DK;
#pragma unroll
        for (int d2 = 0; d2 < DK / 2; d2++) {
            float2 f = upk2(acc2[d2]);
            const float v0 = f.x * inv, v1 = f.y * inv;
            const __nv_bfloat16 h0 = __float2bfloat16(v0);
            const __nv_bfloat16 h1 = __float2bfloat16(v1);
            *(__nv_bfloat162*)&ctx_hi[base + 2 * d2] = __nv_bfloat162(h0, h1);
            *(__nv_bfloat162*)&ctx_lo[base + 2 * d2] = __nv_bfloat162(
                __float2bfloat16(v0 - __bfloat162float(h0)),
                __float2bfloat16(v1 - __bfloat162float(h1)));
        }
    }
}

// ---------------- fused residual add + LayerNorm ----------------
__global__ void add_ln_kernel(const float* __restrict__ a, const float* __restrict__ bsrc,
                              const float* __restrict__ g, const float* __restrict__ beta,
                              float* __restrict__ out)
{
    const int mrow = blockIdx.x;
    const int c = threadIdx.x;
    __shared__ float red[Cc];
    const float v = a[(long)mrow * Cc + c] + bsrc[(long)mrow * Cc + c];
    red[c] = v;
    __syncthreads();
    for (int s = Cc / 2; s > 0; s >>= 1) {
        if (c < s) red[c] += red[c + s];
        __syncthreads();
    }
    const float mean = red[0] * (1.f / (float)Cc);
    __syncthreads();
    const float d = v - mean;
    red[c] = d * d;
    __syncthreads();
    for (int s = Cc / 2; s > 0; s >>= 1) {
        if (c < s) red[c] += red[c + s];
        __syncthreads();
    }
    const float var = red[0] * (1.f / (float)Cc);
    out[(long)mrow * Cc + c] = d * rsqrtf(var + 1e-5f) * g[c] + beta[c];
}

__global__ void add_lnK_kernel(const float* __restrict__ a, const float* __restrict__ pbase,
                               const float* __restrict__ cb,
                               const float* __restrict__ g, const float* __restrict__ beta,
                               float* __restrict__ out)
{
    const int mrow = blockIdx.x;
    const int c = threadIdx.x;
    __shared__ float red[Cc];
    const long off = (long)mrow * Cc + c;
    float v = a[off] + cb[c];
#pragma unroll
    for (int s = 0; s < NSPLIT; s++) v += pbase[off + (size_t)s * NELEM];
    red[c] = v;
    __syncthreads();
    for (int s = Cc / 2; s > 0; s >>= 1) {
        if (c < s) red[c] += red[c + s];
        __syncthreads();
    }
    const float mean = red[0] * (1.f / (float)Cc);
    __syncthreads();
    const float d = v - mean;
    red[c] = d * d;
    __syncthreads();
    for (int s = Cc / 2; s > 0; s >>= 1) {
        if (c < s) red[c] += red[c + s];
        __syncthreads();
    }
    const float var = red[0] * (1.f / (float)Cc);
    out[off] = d * rsqrtf(var + 1e-5f) * g[c] + beta[c];
}

// ---------------- launcher ----------------
extern "C" void kernel_launch(void* const* d_in, const int* in_sizes, int n_in,
                              void* d_out, int out_size)
{
    const float* x        = (const float*)d_in[0];
    const float* wq_proj  = (const float*)d_in[1];
    const float* bq_proj  = (const float*)d_in[2];
    const float* wk_proj  = (const float*)d_in[3];
    const float* bk_proj  = (const float*)d_in[4];
    const float* wv_proj  = (const float*)d_in[5];
    const float* bv_proj  = (const float*)d_in[6];
    const float* wq_a     = (const float*)d_in[7];
    const float* bq_a     = (const float*)d_in[8];
    const float* wk_a     = (const float*)d_in[9];
    const float* bk_a     = (const float*)d_in[10];
    const float* wv_a     = (const float*)d_in[11];
    const float* bv_a     = (const float*)d_in[12];
    const float* wo_a     = (const float*)d_in[13];
    const float* bo_a     = (const float*)d_in[14];
    const float* conv_w   = (const float*)d_in[15];
    const float* conv_b   = (const float*)d_in[16];
    const float* ln1_g    = (const float*)d_in[17];
    const float* ln1_b    = (const float*)d_in[18];
    const float* ln2_g    = (const float*)d_in[19];
    const float* ln2_b    = (const float*)d_in[20];
    float* out = (float*)d_out;

    float* buf = nullptr;   cudaGetSymbolAddress((void**)&buf, g_buf);
    float* loc = nullptr;   cudaGetSymbolAddress((void**)&loc, g_loc);
    float* bsum = nullptr;  cudaGetSymbolAddress((void**)&bsum, g_bsum);
    int*   Rp  = nullptr;   cudaGetSymbolAddress((void**)&Rp, g_R);
    __nv_bfloat16 *xh, *xl, *ah, *al, *cxh, *cxl, *kvh, *kvl, *wth, *wtl, *w8h, *w8l;
    cudaGetSymbolAddress((void**)&xh,  g_x_hi);
    cudaGetSymbolAddress((void**)&xl,  g_x_lo);
    cudaGetSymbolAddress((void**)&ah,  g_act_hi);
    cudaGetSymbolAddress((void**)&al,  g_act_lo);
    cudaGetSymbolAddress((void**)&cxh, g_ctx_hi);
    cudaGetSymbolAddress((void**)&cxl, g_ctx_lo);
    cudaGetSymbolAddress((void**)&kvh, g_kvg_hi);
    cudaGetSymbolAddress((void**)&kvl, g_kvg_lo);
    cudaGetSymbolAddress((void**)&wth, g_wt_hi);
    cudaGetSymbolAddress((void**)&wtl, g_wt_lo);
    cudaGetSymbolAddress((void**)&w8h, g_w8_hi);
    cudaGetSymbolAddress((void**)&w8l, g_w8_lo);

    float* qp    = buf + 0l * NELEM;
    float* kp    = buf + 1l * NELEM;
    float* vp    = buf + 2l * NELEM;
    float* xres  = buf + 3l * NELEM;
    float* q2    = buf + 4l * NELEM;
    float* k2    = buf + 5l * NELEM;
    float* v2    = buf + 6l * NELEM;
    float* rout  = buf + 7l * NELEM;
    float* dummy = buf + 8l * NELEM;
    float* cnvp  = buf + 9l * NELEM;
    float* qloc = loc;
    float* kloc = loc + 16 * Cc;

    // 1: all weight / input decomposition in one launch
    {
        DecompAll da;
        da.w[0] = wq_proj; da.w[1] = wk_proj; da.w[2] = wv_proj;
        da.w[3] = wq_a;    da.w[4] = wk_a;    da.w[5] = wv_a;    da.w[6] = wo_a;
        da.wk = wk_proj;   da.wv = wv_proj;
        da.convw = conv_w; da.x = x;
        da.bk = bk_proj;   da.bv = bv_proj;
        decomp_all_kernel<<<dim3(200, 8, 10), 256>>>(da);
    }

    // 2: q/k/v block projections + fused kvg = x@(wk+wv)+(bk+bv)
    {
        GemmSetT gs;
        for (int i = 0; i < 3; i++) {
            gs.Ah[i] = xh; gs.Al[i] = xl;
            gs.Bh[i] = w8h + i * WSZ; gs.Bl[i] = w8l + i * WSZ;
            gs.Ch[i] = ah + (long)i * NELEM; gs.Cl[i] = al + (long)i * NELEM;
        }
        gs.bias[0] = bq_proj; gs.bias[1] = bk_proj; gs.bias[2] = bv_proj;
        gs.C[0] = qp; gs.C[1] = kp; gs.C[2] = vp;
        gs.Ah[3] = xh; gs.Al[3] = xl;
        gs.Bh[3] = w8h + 7 * WSZ; gs.Bl[3] = w8l + 7 * WSZ;
        gs.bias[3] = bsum; gs.C[3] = dummy;
        gs.Ch[3] = kvh; gs.Cl[3] = kvl;
        gemm_mma_kernel<<<dim3(NROW / 128, Cc / 128, 4), 256>>>(gs);
    }

    // 3: attention head projections
    {
        GemmSetT gs;
        for (int i = 0; i < 3; i++) {
            gs.Ah[i] = ah + (long)i * NELEM; gs.Al[i] = al + (long)i * NELEM;
            gs.Bh[i] = w8h + (3 + i) * WSZ;  gs.Bl[i] = w8l + (3 + i) * WSZ;
            gs.Ch[i] = nullptr; gs.Cl[i] = nullptr;
        }
        gs.bias[0] = bq_a; gs.bias[1] = bk_a; gs.bias[2] = bv_a;
        gs.C[0] = q2; gs.C[1] = k2; gs.C[2] = v2;
        gs.Ah[3] = xh; gs.Al[3] = xl; gs.Bh[3] = w8h; gs.Bl[3] = w8l;
        gs.bias[3] = bq_a; gs.C[3] = dummy; gs.Ch[3] = nullptr; gs.Cl[3] = nullptr;
        gemm_mma_kernel<<<dim3(NROW / 128, Cc / 128, 3), 256>>>(gs);
    }

    // 4: conv via cp.async-pipelined mma.sync (profiled slot)
    conv_mma_kernel<<<dim3(NROW / 128, Cc / 128, NSPLIT), 256>>>(kvh, kvl, wth, wtl, cnvp);

    // 5-6: routing
    pool_kernel<<<Bsz * Pp, Cc>>>(qp, kp, qloc, kloc);
    route_kernel<<<Bsz * Pp, 256>>>(qloc, kloc, Rp);

    // 7: routed attention (emits ctx hi/lo)
    attention_kernel<<<Bsz * Pp * NHh, 256>>>(q2, k2, v2, Rp, cxh, cxl);

    // 8: output projection
    {
        GemmSetT gs;
        gs.Ah[0] = cxh; gs.Al[0] = cxl;
        gs.Bh[0] = w8h + 6 * WSZ; gs.Bl[0] = w8l + 6 * WSZ;
        gs.bias[0] = bo_a; gs.C[0] = rout;
        gs.Ch[0] = nullptr; gs.Cl[0] = nullptr;
        for (int i = 1; i < 4; i++) {
            gs.Ah[i] = cxh; gs.Al[i] = cxl;
            gs.Bh[i] = w8h; gs.Bl[i] = w8l;
            gs.bias[i] = bo_a; gs.C[i] = rout;
            gs.Ch[i] = nullptr; gs.Cl[i] = nullptr;
        }
        gemm_mma_kernel<<<dim3(NROW / 128, Cc / 128, 1), 256>>>(gs);
    }

    // 9-10: LayerNorms
    add_ln_kernel<<<NROW, Cc>>>(x, rout, ln1_g, ln1_b, xres);
    add_lnK_kernel<<<NROW, Cc>>>(xres, cnvp, conv_b, ln2_g, ln2_b, out);
}

// round 9
// speedup vs baseline: 1.0560x; 1.0560x over previous
#include <cuda_runtime.h>
#include <cuda_bf16.h>
#include <math.h>
#include <stdint.h>

// Problem constants
#define Bsz 2
#define Hh  64
#define Ww  24
#define Cc  256
#define Pp  8
#define HP  8
#define NHh 8
#define DK  32
#define KV  4
#define NROW (Bsz*Hh*Ww)       // 3072
#define NELEM (NROW*Cc)        // 786432
#define LBLK (HP*Ww)           // 192
#define LKEY (KV*LBLK)         // 768
#define KTOT (25*Cc)           // 6400 conv K
#define NSPLIT 3
#define NCHUNK 200             // 6400 / 32
#define WSZ ((long)Cc*Cc)

#define QK_SCALE (0.17677669529663687f * 1.44269504088896340f)

// ---------------- device scratch ----------------
// fp32 slots: 0:qp 1:kp 2:vp 3:xres 4:q2 5:k2 6:v2 7:rout 8:dummy 9..11:conv partials
__device__ float g_buf[12u * NELEM];
__device__ float g_loc[2 * 16 * Cc];
__device__ float g_bsum[Cc];
__device__ __nv_bfloat16 g_x_hi[NELEM],   g_x_lo[NELEM];
__device__ __nv_bfloat16 g_act_hi[3u*NELEM], g_act_lo[3u*NELEM];
__device__ __nv_bfloat16 g_ctx_hi[NELEM], g_ctx_lo[NELEM];
__device__ __nv_bfloat16 g_kvg_hi[NELEM], g_kvg_lo[NELEM];
__device__ __nv_bfloat16 g_wt_hi[Cc * KTOT], g_wt_lo[Cc * KTOT];
__device__ __nv_bfloat16 g_w8_hi[8u*Cc*Cc], g_w8_lo[8u*Cc*Cc];

// ---------------- packed f32x2 helpers ----------------
__device__ __forceinline__ unsigned long long pk2(float lo, float hi) {
    unsigned long long r;
    asm("mov.b64 %0, {%1, %2};" : "=l"(r)
        : "r"(__float_as_uint(lo)), "r"(__float_as_uint(hi)));
    return r;
}
__device__ __forceinline__ unsigned long long ffma2(unsigned long long a,
                                                    unsigned long long b,
                                                    unsigned long long c) {
    unsigned long long d;
    asm("fma.rn.f32x2 %0, %1, %2, %3;" : "=l"(d) : "l"(a), "l"(b), "l"(c));
    return d;
}
__device__ __forceinline__ unsigned long long fmul2(unsigned long long a,
                                                    unsigned long long b) {
    unsigned long long d;
    asm("mul.rn.f32x2 %0, %1, %2;" : "=l"(d) : "l"(a), "l"(b));
    return d;
}
__device__ __forceinline__ float2 upk2(unsigned long long v) {
    unsigned int lo, hi;
    asm("mov.b64 {%0, %1}, %2;" : "=r"(lo), "=r"(hi) : "l"(v));
    return make_float2(__uint_as_float(lo), __uint_as_float(hi));
}
__device__ __forceinline__ float ex2f(float x) {
    float r;
    asm("ex2.approx.ftz.f32 %0, %1;" : "=f"(r) : "f"(x));
    return r;
}

// ---------------- warp MMA helpers ----------------
__device__ __forceinline__ uint32_t smem_u32(const void* p) {
    uint32_t a;
    asm("{ .reg .u64 t; cvta.to.shared.u64 t, %1; cvt.u32.u64 %0, t; }"
        : "=r"(a) : "l"(p));
    return a;
}
#define SWZ64(o) ((o) ^ (((o) >> 3) & 0x30))

__device__ __forceinline__ void ldsm4(uint32_t* r, uint32_t addr) {
    asm volatile("ldmatrix.sync.aligned.m8n8.x4.shared.b16 {%0,%1,%2,%3}, [%4];"
                 : "=r"(r[0]), "=r"(r[1]), "=r"(r[2]), "=r"(r[3]) : "r"(addr));
}
__device__ __forceinline__ void mma_bf16(float* c, const uint32_t* a, const uint32_t* b) {
    asm volatile(
        "mma.sync.aligned.m16n8k16.row.col.f32.bf16.bf16.f32 "
        "{%0,%1,%2,%3}, {%4,%5,%6,%7}, {%8,%9}, {%0,%1,%2,%3};"
        : "+f"(c[0]), "+f"(c[1]), "+f"(c[2]), "+f"(c[3])
        : "r"(a[0]), "r"(a[1]), "r"(a[2]), "r"(a[3]), "r"(b[0]), "r"(b[1]));
}

// ================= tensor-core GEMM, 128x128 tile, reg-pipelined K32 (r6-proven) ===========
struct GemmSetT {
    const __nv_bfloat16 *Ah[4], *Al[4], *Bh[4], *Bl[4];
    const float* bias[4];
    float* C[4];
    __nv_bfloat16 *Ch[4], *Cl[4];
};

__global__ __launch_bounds__(256, 1)
void gemm_mma_kernel(GemmSetT gs)
{
    __shared__ char smem[32768];
    const uint32_t sb = smem_u32(smem);
    const uint32_t A_HI = sb, A_LO = sb + 8192, B_HI = sb + 16384, B_LO = sb + 24576;

    const int z = blockIdx.z;
    const __nv_bfloat16* __restrict__ Ah = gs.Ah[z];
    const __nv_bfloat16* __restrict__ Al = gs.Al[z];
    const __nv_bfloat16* __restrict__ Bh = gs.Bh[z];
    const __nv_bfloat16* __restrict__ Bl = gs.Bl[z];
    const float* __restrict__ bias = gs.bias[z];
    float* __restrict__ C = gs.C[z];
    __nv_bfloat16* __restrict__ Ch = gs.Ch[z];
    __nv_bfloat16* __restrict__ Cl = gs.Cl[z];

    const int tid  = threadIdx.x;
    const int wid  = tid >> 5;
    const int lane = tid & 31;
    const int m0 = blockIdx.x * 128;
    const int n0 = blockIdx.y * 128;
    const int wm = wid & 3;
    const int wn = wid >> 2;

    int l_row[2], l_seg[2];
#pragma unroll
    for (int i = 0; i < 2; i++) {
        const int idx = tid + 256 * i;
        l_row[i] = idx >> 2;
        l_seg[i] = idx & 3;
    }

    float acc[2][8][4];
#pragma unroll
    for (int i = 0; i < 2; i++)
#pragma unroll
        for (int j = 0; j < 8; j++)
#pragma unroll
            for (int q = 0; q < 4; q++) acc[i][j][q] = 0.f;

    uint4 rAh[2], rAl[2], rBh[2], rBl[2];
#pragma unroll
    for (int i = 0; i < 2; i++) {
        const long aoff = (long)(m0 + l_row[i]) * Cc + l_seg[i] * 8;
        rAh[i] = *(const uint4*)(Ah + aoff);
        rAl[i] = *(const uint4*)(Al + aoff);
        const long boff = (long)(n0 + l_row[i]) * Cc + l_seg[i] * 8;
        rBh[i] = *(const uint4*)(Bh + boff);
        rBl[i] = *(const uint4*)(Bl + boff);
    }

    for (int c = 0; c < 8; c++) {
        __syncthreads();
#pragma unroll
        for (int i = 0; i < 2; i++) {
            const uint32_t so = SWZ64((uint32_t)(l_row[i] * 64 + l_seg[i] * 16));
            *(uint4*)(smem + so)         = rAh[i];
            *(uint4*)(smem + 8192 + so)  = rAl[i];
            *(uint4*)(smem + 16384 + so) = rBh[i];
            *(uint4*)(smem + 24576 + so) = rBl[i];
        }
        __syncthreads();

        if (c + 1 < 8) {
            const int kb = (c + 1) * 32;
#pragma unroll
            for (int i = 0; i < 2; i++) {
                const long aoff = (long)(m0 + l_row[i]) * Cc + kb + l_seg[i] * 8;
                rAh[i] = *(const uint4*)(Ah + aoff);
                rAl[i] = *(const uint4*)(Al + aoff);
                const long boff = (long)(n0 + l_row[i]) * Cc + kb + l_seg[i] * 8;
                rBh[i] = *(const uint4*)(Bh + boff);
                rBl[i] = *(const uint4*)(Bl + boff);
            }
        }

#pragma unroll
        for (int kst = 0; kst < 2; kst++) {
            uint32_t ahi[2][4], alo[2][4];
#pragma unroll
            for (int mh = 0; mh < 2; mh++) {
                const int tile = lane >> 3;
                const int row = wm * 32 + mh * 16 + ((tile & 1) << 3) + (lane & 7);
                const int unit = kst * 2 + (tile >> 1);
                const uint32_t so = SWZ64((uint32_t)(row * 64 + unit * 16));
                ldsm4(ahi[mh], A_HI + so);
                ldsm4(alo[mh], A_LO + so);
            }
            uint32_t bhi[8][2], blo[8][2];
#pragma unroll
            for (int ng = 0; ng < 4; ng++) {
                const int tile = lane >> 3;
                const int row = wn * 64 + ng * 16 + ((tile >> 1) << 3) + (lane & 7);
                const int unit = kst * 2 + (tile & 1);
                const uint32_t so = SWZ64((uint32_t)(row * 64 + unit * 16));
                uint32_t th[4], tl[4];
                ldsm4(th, B_HI + so);
                ldsm4(tl, B_LO + so);
                bhi[ng * 2][0] = th[0]; bhi[ng * 2][1] = th[1];
                bhi[ng * 2 + 1][0] = th[2]; bhi[ng * 2 + 1][1] = th[3];
                blo[ng * 2][0] = tl[0]; blo[ng * 2][1] = tl[1];
                blo[ng * 2 + 1][0] = tl[2]; blo[ng * 2 + 1][1] = tl[3];
            }
#pragma unroll
            for (int mh = 0; mh < 2; mh++)
#pragma unroll
                for (int nt = 0; nt < 8; nt++) {
                    mma_bf16(acc[mh][nt], ahi[mh], bhi[nt]);
                    mma_bf16(acc[mh][nt], alo[mh], bhi[nt]);
                    mma_bf16(acc[mh][nt], ahi[mh], blo[nt]);
                }
        }
    }

#pragma unroll
    for (int mh = 0; mh < 2; mh++) {
        const int mrow = m0 + wm * 32 + mh * 16 + (lane >> 2);
#pragma unroll
        for (int nt = 0; nt < 8; nt++) {
            const int n = n0 + wn * 64 + nt * 8 + (lane & 3) * 2;
            const float2 bi = *(const float2*)&bias[n];
            const float v0 = acc[mh][nt][0] + bi.x;
            const float v1 = acc[mh][nt][1] + bi.y;
            const float v2 = acc[mh][nt][2] + bi.x;
            const float v3 = acc[mh][nt][3] + bi.y;
            const size_t o0 = (size_t)mrow * Cc + n;
            const size_t o1 = (size_t)(mrow + 8) * Cc + n;
            *(float2*)&C[o0] = make_float2(v0, v1);
            *(float2*)&C[o1] = make_float2(v2, v3);
            if (Ch) {
                const __nv_bfloat16 h0 = __float2bfloat16(v0);
                const __nv_bfloat16 h1 = __float2bfloat16(v1);
                const __nv_bfloat16 h2 = __float2bfloat16(v2);
                const __nv_bfloat16 h3 = __float2bfloat16(v3);
                *(__nv_bfloat162*)&Ch[o0] = __nv_bfloat162(h0, h1);
                *(__nv_bfloat162*)&Ch[o1] = __nv_bfloat162(h2, h3);
                *(__nv_bfloat162*)&Cl[o0] = __nv_bfloat162(
                    __float2bfloat16(v0 - __bfloat162float(h0)),
                    __float2bfloat16(v1 - __bfloat162float(h1)));
                *(__nv_bfloat162*)&Cl[o1] = __nv_bfloat162(
                    __float2bfloat16(v2 - __bfloat162float(h2)),
                    __float2bfloat16(v3 - __bfloat162float(h3)));
            }
        }
    }
}

// ---------------- conv implicit GEMM, 128x128 tile, reg-pipelined K32 (r5-proven) ----------
__global__ __launch_bounds__(256, 1)
void conv_mma_kernel(const __nv_bfloat16* __restrict__ a_hi,
                     const __nv_bfloat16* __restrict__ a_lo,
                     const __nv_bfloat16* __restrict__ b_hi,
                     const __nv_bfloat16* __restrict__ b_lo,
                     float* __restrict__ part)
{
    __shared__ char smem[32768];
    const uint32_t sb = smem_u32(smem);
    const uint32_t A_HI = sb, A_LO = sb + 8192, B_HI = sb + 16384, B_LO = sb + 24576;

    const int tid  = threadIdx.x;
    const int wid  = tid >> 5;
    const int lane = tid & 31;
    const int m0 = blockIdx.x * 128;
    const int n0 = blockIdx.y * 128;
    const int z  = blockIdx.z;
    const int cbeg = (z * NCHUNK) / 3;
    const int cend = ((z + 1) * NCHUNK) / 3;

    const int wm = wid & 3;
    const int wn = wid >> 2;

    int a_row[2], a_seg[2], a_h[2], a_w[2];
    long a_base[2];
    int b_rw[2], b_sg[2];
#pragma unroll
    for (int i = 0; i < 2; i++) {
        const int idx = tid + 256 * i;
        a_row[i] = idx >> 2;
        a_seg[i] = idx & 3;
        const int m = m0 + a_row[i];
        const int b = m / (Hh * Ww);
        a_h[i] = (m / Ww) % Hh;
        a_w[i] = m % Ww;
        a_base[i] = (long)b * Hh * Ww * Cc;
        b_rw[i] = idx >> 2;
        b_sg[i] = idx & 3;
    }

    float acc[2][8][4];
#pragma unroll
    for (int i = 0; i < 2; i++)
#pragma unroll
        for (int j = 0; j < 8; j++)
#pragma unroll
            for (int q = 0; q < 4; q++) acc[i][j][q] = 0.f;

    uint4 rAh[2], rAl[2], rBh[2], rBl[2];
    {
        const int kb = cbeg * 32;
        const int patch = kb >> 8;
        const int kh = patch / 5, kw = patch % 5;
        const int ci0 = kb & 255;
#pragma unroll
        for (int i = 0; i < 2; i++) {
            const int hh = a_h[i] + kh - 2;
            const int ww = a_w[i] + kw - 2;
            if (hh >= 0 && hh < Hh && ww >= 0 && ww < Ww) {
                const long off = a_base[i] + ((long)hh * Ww + ww) * Cc + ci0 + a_seg[i] * 8;
                rAh[i] = *(const uint4*)(a_hi + off);
                rAl[i] = *(const uint4*)(a_lo + off);
            } else {
                rAh[i] = make_uint4(0, 0, 0, 0);
                rAl[i] = make_uint4(0, 0, 0, 0);
            }
            const long boff = (long)(n0 + b_rw[i]) * KTOT + kb + b_sg[i] * 8;
            rBh[i] = *(const uint4*)(b_hi + boff);
            rBl[i] = *(const uint4*)(b_lo + boff);
        }
    }

    for (int c = cbeg; c < cend; c++) {
        __syncthreads();
#pragma unroll
        for (int i = 0; i < 2; i++) {
            const uint32_t soA = SWZ64((uint32_t)(a_row[i] * 64 + a_seg[i] * 16));
            *(uint4*)(smem + soA)        = rAh[i];
            *(uint4*)(smem + 8192 + soA) = rAl[i];
            const uint32_t soB = SWZ64((uint32_t)(b_rw[i] * 64 + b_sg[i] * 16));
            *(uint4*)(smem + 16384 + soB) = rBh[i];
            *(uint4*)(smem + 24576 + soB) = rBl[i];
        }
        __syncthreads();

        if (c + 1 < cend) {
            const int kb = (c + 1) * 32;
            const int patch = kb >> 8;
            const int kh = patch / 5, kw = patch % 5;
            const int ci0 = kb & 255;
#pragma unroll
            for (int i = 0; i < 2; i++) {
                const int hh = a_h[i] + kh - 2;
                const int ww = a_w[i] + kw - 2;
                if (hh >= 0 && hh < Hh && ww >= 0 && ww < Ww) {
                    const long off = a_base[i] + ((long)hh * Ww + ww) * Cc + ci0 + a_seg[i] * 8;
                    rAh[i] = *(const uint4*)(a_hi + off);
                    rAl[i] = *(const uint4*)(a_lo + off);
                } else {
                    rAh[i] = make_uint4(0, 0, 0, 0);
                    rAl[i] = make_uint4(0, 0, 0, 0);
                }
                const long boff = (long)(n0 + b_rw[i]) * KTOT + kb + b_sg[i] * 8;
                rBh[i] = *(const uint4*)(b_hi + boff);
                rBl[i] = *(const uint4*)(b_lo + boff);
            }
        }

#pragma unroll
        for (int kst = 0; kst < 2; kst++) {
            uint32_t ahi[2][4], alo[2][4];
#pragma unroll
            for (int mh = 0; mh < 2; mh++) {
                const int tile = lane >> 3;
                const int row = wm * 32 + mh * 16 + ((tile & 1) << 3) + (lane & 7);
                const int unit = kst * 2 + (tile >> 1);
                const uint32_t so = SWZ64((uint32_t)(row * 64 + unit * 16));
                ldsm4(ahi[mh], A_HI + so);
                ldsm4(alo[mh], A_LO + so);
            }
            uint32_t bhi[8][2], blo[8][2];
#pragma unroll
            for (int ng = 0; ng < 4; ng++) {
                const int tile = lane >> 3;
                const int row = wn * 64 + ng * 16 + ((tile >> 1) << 3) + (lane & 7);
                const int unit = kst * 2 + (tile & 1);
                const uint32_t so = SWZ64((uint32_t)(row * 64 + unit * 16));
                uint32_t th[4], tl[4];
                ldsm4(th, B_HI + so);
                ldsm4(tl, B_LO + so);
                bhi[ng * 2][0] = th[0]; bhi[ng * 2][1] = th[1];
                bhi[ng * 2 + 1][0] = th[2]; bhi[ng * 2 + 1][1] = th[3];
                blo[ng * 2][0] = tl[0]; blo[ng * 2][1] = tl[1];
                blo[ng * 2 + 1][0] = tl[2]; blo[ng * 2 + 1][1] = tl[3];
            }
#pragma unroll
            for (int mh = 0; mh < 2; mh++)
#pragma unroll
                for (int nt = 0; nt < 8; nt++) {
                    mma_bf16(acc[mh][nt], ahi[mh], bhi[nt]);
                    mma_bf16(acc[mh][nt], alo[mh], bhi[nt]);
                    mma_bf16(acc[mh][nt], ahi[mh], blo[nt]);
                }
        }
    }

    float* base = part + (size_t)z * NELEM;
#pragma unroll
    for (int mh = 0; mh < 2; mh++) {
        const int mrow = m0 + wm * 32 + mh * 16 + (lane >> 2);
#pragma unroll
        for (int nt = 0; nt < 8; nt++) {
            const int n = n0 + wn * 64 + nt * 8 + (lane & 3) * 2;
            *(float2*)&base[(size_t)mrow * Cc + n] =
                make_float2(acc[mh][nt][0], acc[mh][nt][1]);
            *(float2*)&base[(size_t)(mrow + 8) * Cc + n] =
                make_float2(acc[mh][nt][2], acc[mh][nt][3]);
        }
    }
}

// ---------------- fused decompose: 8 proj weights + conv weight + x ----------------
struct DecompAll {
    const float *w[7];
    const float *wk, *wv;
    const float *convw;
    const float *x;
    const float *bk, *bv;
};

__global__ void decomp_all_kernel(DecompAll da)
{
    const int z = blockIdx.z;
    const int bx = blockIdx.x, by = blockIdx.y;
    const int tid = threadIdx.x;
    const int tx = tid & 31, ty = tid >> 5;

    if (z <= 7) {
        if (bx >= 8) return;
        if (z == 7 && bx == 0 && by == 0)
            g_bsum[tid] = da.bk[tid] + da.bv[tid];
        __shared__ float tile[32][33];
        const int k0 = bx * 32, n0 = by * 32;
#pragma unroll
        for (int i = 0; i < 4; i++) {
            const long off = (long)(k0 + ty + i * 8) * Cc + n0 + tx;
            tile[ty + i * 8][tx] = (z < 7) ? da.w[z][off] : (da.wk[off] + da.wv[off]);
        }
        __syncthreads();
#pragma unroll
        for (int i = 0; i < 4; i++) {
            const float v = tile[tx][ty + i * 8];
            const __nv_bfloat16 h = __float2bfloat16(v);
            const long o = (long)z * WSZ + (long)(n0 + ty + i * 8) * Cc + k0 + tx;
            g_w8_hi[o] = h;
            g_w8_lo[o] = __float2bfloat16(v - __bfloat162float(h));
        }
    } else if (z == 8) {
        __shared__ float tile[32][33];
        const int k0 = bx * 32, n0 = by * 32;
#pragma unroll
        for (int i = 0; i < 4; i++)
            tile[ty + i * 8][tx] = da.convw[(long)(k0 + ty + i * 8) * Cc + n0 + tx];
        __syncthreads();
#pragma unroll
        for (int i = 0; i < 4; i++) {
            const float v = tile[tx][ty + i * 8];
            const __nv_bfloat16 h = __float2bfloat16(v);
            const long o = (long)(n0 + ty + i * 8) * KTOT + k0 + tx;
            g_wt_hi[o] = h;
            g_wt_lo[o] = __float2bfloat16(v - __bfloat162float(h));
        }
    } else {
        const int idx = (by * 200 + bx) * 256 + tid;
        if (idx < NELEM / 4) {
            const float4 v = ((const float4*)da.x)[idx];
            __nv_bfloat16 h0 = __float2bfloat16(v.x), h1 = __float2bfloat16(v.y);
            __nv_bfloat16 h2 = __float2bfloat16(v.z), h3 = __float2bfloat16(v.w);
            ((__nv_bfloat162*)g_x_hi)[idx * 2]     = __nv_bfloat162(h0, h1);
            ((__nv_bfloat162*)g_x_hi)[idx * 2 + 1] = __nv_bfloat162(h2, h3);
            ((__nv_bfloat162*)g_x_lo)[idx * 2]     = __nv_bfloat162(
                __float2bfloat16(v.x - __bfloat162float(h0)),
                __float2bfloat16(v.y - __bfloat162float(h1)));
            ((__nv_bfloat162*)g_x_lo)[idx * 2 + 1] = __nv_bfloat162(
                __float2bfloat16(v.z - __bfloat162float(h2)),
                __float2bfloat16(v.w - __bfloat162float(h3)));
        }
    }
}

// ---------------- block mean pooling ----------------
__global__ void pool_kernel(const float* __restrict__ qp, const float* __restrict__ kp,
                            float* __restrict__ qloc, float* __restrict__ kloc)
{
    const int bp = blockIdx.x;
    const int c  = threadIdx.x;
    const float* qb = qp + (long)bp * LBLK * Cc + c;
    const float* kb = kp + (long)bp * LBLK * Cc + c;
    float sq = 0.f, sk = 0.f;
    for (int i = 0; i < LBLK; i++) { sq += qb[i * Cc]; sk += kb[i * Cc]; }
    qloc[bp * Cc + c] = sq * (1.f / (float)LBLK);
    kloc[bp * Cc + c] = sk * (1.f / (float)LBLK);
}

// ---------------- attention with inline routing (MUFU ex2, writes ctx hi/lo) ----------------
#define KCHUNK 128
__global__ void attention_kernel(const float* __restrict__ q2,
                                 const float* __restrict__ k2,
                                 const float* __restrict__ v2,
                                 const float* __restrict__ qloc,
                                 const float* __restrict__ kloc,
                                 __nv_bfloat16* __restrict__ ctx_hi,
                                 __nv_bfloat16* __restrict__ ctx_lo)
{
    __shared__ float Ks[KCHUNK * DK];
    __shared__ float Vs[KCHUNK * DK];
    __shared__ float Sl[8];
    __shared__ int   Rs[KV];

    const int blk = blockIdx.x;
    const int h = blk % NHh;
    const int p = (blk / NHh) % Pp;
    const int b = blk / (NHh * Pp);
    const int tid = threadIdx.x;
    const int wid = tid >> 5;
    const int lane = tid & 31;

    // inline routing: warp j computes qloc[bp] . kloc[b*8+j], thread 0 does top-4
    {
        const float* q = qloc + (b * Pp + p) * Cc;
        const float* k = kloc + (b * Pp + wid) * Cc;
        float partial = 0.f;
#pragma unroll
        for (int c = lane; c < Cc; c += 32) partial += q[c] * k[c];
#pragma unroll
        for (int o = 16; o; o >>= 1) partial += __shfl_xor_sync(0xffffffff, partial, o);
        if (lane == 0) Sl[wid] = partial;
        __syncthreads();
        if (tid == 0) {
            bool used[8] = {};
            for (int t = 0; t < KV; t++) {
                int best = 0; float bv = -1e30f;
                for (int j = 0; j < Pp; j++)
                    if (!used[j] && Sl[j] > bv) { bv = Sl[j]; best = j; }
                used[best] = true;
                Rs[t] = best;
            }
        }
        // Rs becomes visible at the first __syncthreads of the main loop
    }

    const bool active = (tid < LBLK);
    unsigned long long qv2[DK / 2], acc2[DK / 2];
    float m = -1e30f, l = 0.f;
    if (active) {
        const float* qrow = q2 + ((long)((b * Pp + p) * LBLK + tid)) * Cc + h * DK;
#pragma unroll
        for (int d2 = 0; d2 < DK / 2; d2++) {
            qv2[d2] = pk2(qrow[2 * d2] * QK_SCALE, qrow[2 * d2 + 1] * QK_SCALE);
            acc2[d2] = 0ull;
        }
    }

    for (int ch = 0; ch < LKEY / KCHUNK; ch++) {
        __syncthreads();
        const int kg0 = ch * KCHUNK;
        for (int i = tid; i < KCHUNK * (DK / 4); i += blockDim.x) {
            const int row = i >> 3;
            const int d4  = (i & 7) * 4;
            const int kg  = kg0 + row;
            const int ks  = kg / LBLK;
            const int rr  = kg - ks * LBLK;
            const int r   = Rs[ks];
            const long base = ((long)(b * Pp + r) * LBLK + rr) * Cc + h * DK + d4;
            *(float4*)&Ks[row * DK + d4] = *(const float4*)&k2[base];
            *(float4*)&Vs[row * DK + d4] = *(const float4*)&v2[base];
        }
        __syncthreads();
        if (active) {
            for (int k = 0; k < KCHUNK; k++) {
                const unsigned long long* kr = (const unsigned long long*)&Ks[k * DK];
                unsigned long long s0 = 0ull, s1 = 0ull, s2 = 0ull, s3 = 0ull;
#pragma unroll
                for (int d2 = 0; d2 < DK / 2; d2 += 4) {
                    s0 = ffma2(qv2[d2 + 0], kr[d2 + 0], s0);
                    s1 = ffma2(qv2[d2 + 1], kr[d2 + 1], s1);
                    s2 = ffma2(qv2[d2 + 2], kr[d2 + 2], s2);
                    s3 = ffma2(qv2[d2 + 3], kr[d2 + 3], s3);
                }
                const float2 f0 = upk2(s0), f1 = upk2(s1), f2 = upk2(s2), f3 = upk2(s3);
                const float s = ((f0.x + f0.y) + (f1.x + f1.y)) + ((f2.x + f2.y) + (f3.x + f3.y));
                const float mnew = fmaxf(m, s);
                const float corr = ex2f(m - mnew);
                const float pe   = ex2f(s - mnew);
                l = fmaf(l, corr, pe);
                const unsigned long long cc = pk2(corr, corr);
                const unsigned long long pp = pk2(pe, pe);
                const unsigned long long* vr = (const unsigned long long*)&Vs[k * DK];
#pragma unroll
                for (int d2 = 0; d2 < DK / 2; d2++)
                    acc2[d2] = ffma2(acc2[d2], cc, fmul2(pp, vr[d2]));
                m = mnew;
            }
        }
    }

    if (active) {
        const float inv = 1.0f / l;
        const long base = ((long)((b * Pp + p) * LBLK + tid)) * Cc + h * DK;
#pragma unroll
        for (int d2 = 0; d2 < DK / 2; d2++) {
            float2 f = upk2(acc2[d2]);
            const float v0 = f.x * inv, v1 = f.y * inv;
            const __nv_bfloat16 h0 = __float2bfloat16(v0);
            const __nv_bfloat16 h1 = __float2bfloat16(v1);
            *(__nv_bfloat162*)&ctx_hi[base + 2 * d2] = __nv_bfloat162(h0, h1);
            *(__nv_bfloat162*)&ctx_lo[base + 2 * d2] = __nv_bfloat162(
                __float2bfloat16(v0 - __bfloat162float(h0)),
                __float2bfloat16(v1 - __bfloat162float(h1)));
        }
    }
}

// ---------------- fused residual add + LayerNorm ----------------
__global__ void add_ln_kernel(const float* __restrict__ a, const float* __restrict__ bsrc,
                              const float* __restrict__ g, const float* __restrict__ beta,
                              float* __restrict__ out)
{
    const int mrow = blockIdx.x;
    const int c = threadIdx.x;
    __shared__ float red[Cc];
    const float v = a[(long)mrow * Cc + c] + bsrc[(long)mrow * Cc + c];
    red[c] = v;
    __syncthreads();
    for (int s = Cc / 2; s > 0; s >>= 1) {
        if (c < s) red[c] += red[c + s];
        __syncthreads();
    }
    const float mean = red[0] * (1.f / (float)Cc);
    __syncthreads();
    const float d = v - mean;
    red[c] = d * d;
    __syncthreads();
    for (int s = Cc / 2; s > 0; s >>= 1) {
        if (c < s) red[c] += red[c + s];
        __syncthreads();
    }
    const float var = red[0] * (1.f / (float)Cc);
    out[(long)mrow * Cc + c] = d * rsqrtf(var + 1e-5f) * g[c] + beta[c];
}

__global__ void add_lnK_kernel(const float* __restrict__ a, const float* __restrict__ pbase,
                               const float* __restrict__ cb,
                               const float* __restrict__ g, const float* __restrict__ beta,
                               float* __restrict__ out)
{
    const int mrow = blockIdx.x;
    const int c = threadIdx.x;
    __shared__ float red[Cc];
    const long off = (long)mrow * Cc + c;
    float v = a[off] + cb[c];
#pragma unroll
    for (int s = 0; s < NSPLIT; s++) v += pbase[off + (size_t)s * NELEM];
    red[c] = v;
    __syncthreads();
    for (int s = Cc / 2; s > 0; s >>= 1) {
        if (c < s) red[c] += red[c + s];
        __syncthreads();
    }
    const float mean = red[0] * (1.f / (float)Cc);
    __syncthreads();
    const float d = v - mean;
    red[c] = d * d;
    __syncthreads();
    for (int s = Cc / 2; s > 0; s >>= 1) {
        if (c < s) red[c] += red[c + s];
        __syncthreads();
    }
    const float var = red[0] * (1.f / (float)Cc);
    out[off] = d * rsqrtf(var + 1e-5f) * g[c] + beta[c];
}

// ---------------- launcher ----------------
extern "C" void kernel_launch(void* const* d_in, const int* in_sizes, int n_in,
                              void* d_out, int out_size)
{
    const float* x        = (const float*)d_in[0];
    const float* wq_proj  = (const float*)d_in[1];
    const float* bq_proj  = (const float*)d_in[2];
    const float* wk_proj  = (const float*)d_in[3];
    const float* bk_proj  = (const float*)d_in[4];
    const float* wv_proj  = (const float*)d_in[5];
    const float* bv_proj  = (const float*)d_in[6];
    const float* wq_a     = (const float*)d_in[7];
    const float* bq_a     = (const float*)d_in[8];
    const float* wk_a     = (const float*)d_in[9];
    const float* bk_a     = (const float*)d_in[10];
    const float* wv_a     = (const float*)d_in[11];
    const float* bv_a     = (const float*)d_in[12];
    const float* wo_a     = (const float*)d_in[13];
    const float* bo_a     = (const float*)d_in[14];
    const float* conv_w   = (const float*)d_in[15];
    const float* conv_b   = (const float*)d_in[16];
    const float* ln1_g    = (const float*)d_in[17];
    const float* ln1_b    = (const float*)d_in[18];
    const float* ln2_g    = (const float*)d_in[19];
    const float* ln2_b    = (const float*)d_in[20];
    float* out = (float*)d_out;

    float* buf = nullptr;   cudaGetSymbolAddress((void**)&buf, g_buf);
    float* loc = nullptr;   cudaGetSymbolAddress((void**)&loc, g_loc);
    float* bsum = nullptr;  cudaGetSymbolAddress((void**)&bsum, g_bsum);
    __nv_bfloat16 *xh, *xl, *ah, *al, *cxh, *cxl, *kvh, *kvl, *wth, *wtl, *w8h, *w8l;
    cudaGetSymbolAddress((void**)&xh,  g_x_hi);
    cudaGetSymbolAddress((void**)&xl,  g_x_lo);
    cudaGetSymbolAddress((void**)&ah,  g_act_hi);
    cudaGetSymbolAddress((void**)&al,  g_act_lo);
    cudaGetSymbolAddress((void**)&cxh, g_ctx_hi);
    cudaGetSymbolAddress((void**)&cxl, g_ctx_lo);
    cudaGetSymbolAddress((void**)&kvh, g_kvg_hi);
    cudaGetSymbolAddress((void**)&kvl, g_kvg_lo);
    cudaGetSymbolAddress((void**)&wth, g_wt_hi);
    cudaGetSymbolAddress((void**)&wtl, g_wt_lo);
    cudaGetSymbolAddress((void**)&w8h, g_w8_hi);
    cudaGetSymbolAddress((void**)&w8l, g_w8_lo);

    float* qp    = buf + 0l * NELEM;
    float* kp    = buf + 1l * NELEM;
    float* vp    = buf + 2l * NELEM;
    float* xres  = buf + 3l * NELEM;
    float* q2    = buf + 4l * NELEM;
    float* k2    = buf + 5l * NELEM;
    float* v2    = buf + 6l * NELEM;
    float* rout  = buf + 7l * NELEM;
    float* dummy = buf + 8l * NELEM;
    float* cnvp  = buf + 9l * NELEM;
    float* qloc = loc;
    float* kloc = loc + 16 * Cc;

    // 1: all weight / input decomposition in one launch
    {
        DecompAll da;
        da.w[0] = wq_proj; da.w[1] = wk_proj; da.w[2] = wv_proj;
        da.w[3] = wq_a;    da.w[4] = wk_a;    da.w[5] = wv_a;    da.w[6] = wo_a;
        da.wk = wk_proj;   da.wv = wv_proj;
        da.convw = conv_w; da.x = x;
        da.bk = bk_proj;   da.bv = bv_proj;
        decomp_all_kernel<<<dim3(200, 8, 10), 256>>>(da);
    }

    // 2: q/k/v block projections + fused kvg = x@(wk+wv)+(bk+bv)
    {
        GemmSetT gs;
        for (int i = 0; i < 3; i++) {
            gs.Ah[i] = xh; gs.Al[i] = xl;
            gs.Bh[i] = w8h + i * WSZ; gs.Bl[i] = w8l + i * WSZ;
            gs.Ch[i] = ah + (long)i * NELEM; gs.Cl[i] = al + (long)i * NELEM;
        }
        gs.bias[0] = bq_proj; gs.bias[1] = bk_proj; gs.bias[2] = bv_proj;
        gs.C[0] = qp; gs.C[1] = kp; gs.C[2] = vp;
        gs.Ah[3] = xh; gs.Al[3] = xl;
        gs.Bh[3] = w8h + 7 * WSZ; gs.Bl[3] = w8l + 7 * WSZ;
        gs.bias[3] = bsum; gs.C[3] = dummy;
        gs.Ch[3] = kvh; gs.Cl[3] = kvl;
        gemm_mma_kernel<<<dim3(NROW / 128, Cc / 128, 4), 256>>>(gs);
    }

    // 3: attention head projections
    {
        GemmSetT gs;
        for (int i = 0; i < 3; i++) {
            gs.Ah[i] = ah + (long)i * NELEM; gs.Al[i] = al + (long)i * NELEM;
            gs.Bh[i] = w8h + (3 + i) * WSZ;  gs.Bl[i] = w8l + (3 + i) * WSZ;
            gs.Ch[i] = nullptr; gs.Cl[i] = nullptr;
        }
        gs.bias[0] = bq_a; gs.bias[1] = bk_a; gs.bias[2] = bv_a;
        gs.C[0] = q2; gs.C[1] = k2; gs.C[2] = v2;
        gs.Ah[3] = xh; gs.Al[3] = xl; gs.Bh[3] = w8h; gs.Bl[3] = w8l;
        gs.bias[3] = bq_a; gs.C[3] = dummy; gs.Ch[3] = nullptr; gs.Cl[3] = nullptr;
        gemm_mma_kernel<<<dim3(NROW / 128, Cc / 128, 3), 256>>>(gs);
    }

    // 4: conv via reg-pipelined mma.sync (profiled slot)
    conv_mma_kernel<<<dim3(NROW / 128, Cc / 128, NSPLIT), 256>>>(kvh, kvl, wth, wtl, cnvp);

    // 5: pooling
    pool_kernel<<<Bsz * Pp, Cc>>>(qp, kp, qloc, kloc);

    // 6: routed attention (routing computed inline)
    attention_kernel<<<Bsz * Pp * NHh, 256>>>(q2, k2, v2, qloc, kloc, cxh, cxl);

    // 7: output projection
    {
        GemmSetT gs;
        gs.Ah[0] = cxh; gs.Al[0] = cxl;
        gs.Bh[0] = w8h + 6 * WSZ; gs.Bl[0] = w8l + 6 * WSZ;
        gs.bias[0] = bo_a; gs.C[0] = rout;
        gs.Ch[0] = nullptr; gs.Cl[0] = nullptr;
        for (int i = 1; i < 4; i++) {
            gs.Ah[i] = cxh; gs.Al[i] = cxl;
            gs.Bh[i] = w8h; gs.Bl[i] = w8l;
            gs.bias[i] = bo_a; gs.C[i] = rout;
            gs.Ch[i] = nullptr; gs.Cl[i] = nullptr;
        }
        gemm_mma_kernel<<<dim3(NROW / 128, Cc / 128, 1), 256>>>(gs);
    }

    // 8-9: LayerNorms
    add_ln_kernel<<<NROW, Cc>>>(x, rout, ln1_g, ln1_b, xres);
    add_lnK_kernel<<<NROW, Cc>>>(xres, cnvp, conv_b, ln2_g, ln2_b, out);
}

// round 10
// speedup vs baseline: 1.2456x; 1.1795x over previous
#include <cuda_runtime.h>
#include <cuda_bf16.h>
#include <math.h>
#include <stdint.h>

// Problem constants
#define Bsz 2
#define Hh  64
#define Ww  24
#define Cc  256
#define Pp  8
#define HP  8
#define NHh 8
#define DK  32
#define KV  4
#define NROW (Bsz*Hh*Ww)       // 3072
#define NELEM (NROW*Cc)        // 786432
#define LBLK (HP*Ww)           // 192
#define LKEY (KV*LBLK)         // 768
#define KTOT (25*Cc)           // 6400 conv K
#define NSPLIT 3
#define NCHUNK 200             // 6400 / 32
#define WSZ ((long)Cc*Cc)

#define QK_SCALE (0.17677669529663687f * 1.44269504088896340f)

// ---------------- device scratch ----------------
// fp32 slots: 0:qp 1:kp 2:vp 3:xres 4:q2 5:k2 6:v2 7:rout 8..10:conv partials
__device__ float g_buf[11u * NELEM];
__device__ float g_loc[2 * 16 * Cc];
__device__ int   g_R[Bsz * Pp * KV];
__device__ __nv_bfloat16 g_x_hi[NELEM],   g_x_lo[NELEM];
__device__ __nv_bfloat16 g_act_hi[3u*NELEM], g_act_lo[3u*NELEM];
__device__ __nv_bfloat16 g_ctx_hi[NELEM], g_ctx_lo[NELEM];
__device__ __nv_bfloat16 g_kvg_hi[NELEM], g_kvg_lo[NELEM];
__device__ __nv_bfloat16 g_wt_hi[Cc * KTOT], g_wt_lo[Cc * KTOT];
__device__ __nv_bfloat16 g_w7_hi[7u*Cc*Cc], g_w7_lo[7u*Cc*Cc];

// ---------------- packed f32x2 helpers ----------------
__device__ __forceinline__ unsigned long long pk2(float lo, float hi) {
    unsigned long long r;
    asm("mov.b64 %0, {%1, %2};" : "=l"(r)
        : "r"(__float_as_uint(lo)), "r"(__float_as_uint(hi)));
    return r;
}
__device__ __forceinline__ unsigned long long ffma2(unsigned long long a,
                                                    unsigned long long b,
                                                    unsigned long long c) {
    unsigned long long d;
    asm("fma.rn.f32x2 %0, %1, %2, %3;" : "=l"(d) : "l"(a), "l"(b), "l"(c));
    return d;
}
__device__ __forceinline__ unsigned long long fmul2(unsigned long long a,
                                                    unsigned long long b) {
    unsigned long long d;
    asm("mul.rn.f32x2 %0, %1, %2;" : "=l"(d) : "l"(a), "l"(b));
    return d;
}
__device__ __forceinline__ float2 upk2(unsigned long long v) {
    unsigned int lo, hi;
    asm("mov.b64 {%0, %1}, %2;" : "=r"(lo), "=r"(hi) : "l"(v));
    return make_float2(__uint_as_float(lo), __uint_as_float(hi));
}
__device__ __forceinline__ float ex2f(float x) {
    float r;
    asm("ex2.approx.ftz.f32 %0, %1;" : "=f"(r) : "f"(x));
    return r;
}

// ---------------- warp MMA helpers ----------------
__device__ __forceinline__ uint32_t smem_u32(const void* p) {
    uint32_t a;
    asm("{ .reg .u64 t; cvta.to.shared.u64 t, %1; cvt.u32.u64 %0, t; }"
        : "=r"(a) : "l"(p));
    return a;
}
#define SWZ64(o) ((o) ^ (((o) >> 3) & 0x30))

__device__ __forceinline__ void ldsm4(uint32_t* r, uint32_t addr) {
    asm volatile("ldmatrix.sync.aligned.m8n8.x4.shared.b16 {%0,%1,%2,%3}, [%4];"
                 : "=r"(r[0]), "=r"(r[1]), "=r"(r[2]), "=r"(r[3]) : "r"(addr));
}
__device__ __forceinline__ void mma_bf16(float* c, const uint32_t* a, const uint32_t* b) {
    asm volatile(
        "mma.sync.aligned.m16n8k16.row.col.f32.bf16.bf16.f32 "
        "{%0,%1,%2,%3}, {%4,%5,%6,%7}, {%8,%9}, {%0,%1,%2,%3};"
        : "+f"(c[0]), "+f"(c[1]), "+f"(c[2]), "+f"(c[3])
        : "r"(a[0]), "r"(a[1]), "r"(a[2]), "r"(a[3]), "r"(b[0]), "r"(b[1]));
}

// ================= tensor-core projection GEMM (hi/lo split), r5-proven ===============
struct GemmSetT {
    const __nv_bfloat16 *Ah[3], *Al[3], *Bh[3], *Bl[3];
    const float* bias[3];
    float* C[3];
    __nv_bfloat16 *Ch[3], *Cl[3];   // optional (null => skip)
};

__global__ __launch_bounds__(256, 1)
void gemm_mma_kernel(GemmSetT gs)
{
    __shared__ char smem[32768];
    const uint32_t sb = smem_u32(smem);
    const uint32_t A_HI = sb, A_LO = sb + 8192, B_HI = sb + 16384, B_LO = sb + 24576;

    const int z = blockIdx.z;
    const __nv_bfloat16* __restrict__ Ah = gs.Ah[z];
    const __nv_bfloat16* __restrict__ Al = gs.Al[z];
    const __nv_bfloat16* __restrict__ Bh = gs.Bh[z];
    const __nv_bfloat16* __restrict__ Bl = gs.Bl[z];
    const float* __restrict__ bias = gs.bias[z];
    float* __restrict__ C = gs.C[z];
    __nv_bfloat16* __restrict__ Ch = gs.Ch[z];
    __nv_bfloat16* __restrict__ Cl = gs.Cl[z];

    const int tid  = threadIdx.x;
    const int wid  = tid >> 5;
    const int lane = tid & 31;
    const int m0 = blockIdx.x * 128;
    const int n0 = blockIdx.y * 128;
    const int wm = wid & 3;
    const int wn = wid >> 2;

    int l_row[2], l_seg[2];
#pragma unroll
    for (int i = 0; i < 2; i++) {
        const int idx = tid + 256 * i;
        l_row[i] = idx >> 2;
        l_seg[i] = idx & 3;
    }

    float acc[2][8][4];
#pragma unroll
    for (int i = 0; i < 2; i++)
#pragma unroll
        for (int j = 0; j < 8; j++)
#pragma unroll
            for (int q = 0; q < 4; q++) acc[i][j][q] = 0.f;

    uint4 rAh[2], rAl[2], rBh[2], rBl[2];
#pragma unroll
    for (int i = 0; i < 2; i++) {
        const long aoff = (long)(m0 + l_row[i]) * Cc + l_seg[i] * 8;
        rAh[i] = *(const uint4*)(Ah + aoff);
        rAl[i] = *(const uint4*)(Al + aoff);
        const long boff = (long)(n0 + l_row[i]) * Cc + l_seg[i] * 8;
        rBh[i] = *(const uint4*)(Bh + boff);
        rBl[i] = *(const uint4*)(Bl + boff);
    }

    for (int c = 0; c < 8; c++) {
        __syncthreads();
#pragma unroll
        for (int i = 0; i < 2; i++) {
            const uint32_t so = SWZ64((uint32_t)(l_row[i] * 64 + l_seg[i] * 16));
            *(uint4*)(smem + so)         = rAh[i];
            *(uint4*)(smem + 8192 + so)  = rAl[i];
            *(uint4*)(smem + 16384 + so) = rBh[i];
            *(uint4*)(smem + 24576 + so) = rBl[i];
        }
        __syncthreads();

        if (c + 1 < 8) {
            const int kb = (c + 1) * 32;
#pragma unroll
            for (int i = 0; i < 2; i++) {
                const long aoff = (long)(m0 + l_row[i]) * Cc + kb + l_seg[i] * 8;
                rAh[i] = *(const uint4*)(Ah + aoff);
                rAl[i] = *(const uint4*)(Al + aoff);
                const long boff = (long)(n0 + l_row[i]) * Cc + kb + l_seg[i] * 8;
                rBh[i] = *(const uint4*)(Bh + boff);
                rBl[i] = *(const uint4*)(Bl + boff);
            }
        }

#pragma unroll
        for (int kst = 0; kst < 2; kst++) {
            uint32_t ahi[2][4], alo[2][4];
#pragma unroll
            for (int mh = 0; mh < 2; mh++) {
                const int tile = lane >> 3;
                const int row = wm * 32 + mh * 16 + ((tile & 1) << 3) + (lane & 7);
                const int unit = kst * 2 + (tile >> 1);
                const uint32_t so = SWZ64((uint32_t)(row * 64 + unit * 16));
                ldsm4(ahi[mh], A_HI + so);
                ldsm4(alo[mh], A_LO + so);
            }
            uint32_t bhi[8][2], blo[8][2];
#pragma unroll
            for (int ng = 0; ng < 4; ng++) {
                const int tile = lane >> 3;
                const int row = wn * 64 + ng * 16 + ((tile >> 1) << 3) + (lane & 7);
                const int unit = kst * 2 + (tile & 1);
                const uint32_t so = SWZ64((uint32_t)(row * 64 + unit * 16));
                uint32_t th[4], tl[4];
                ldsm4(th, B_HI + so);
                ldsm4(tl, B_LO + so);
                bhi[ng * 2][0] = th[0]; bhi[ng * 2][1] = th[1];
                bhi[ng * 2 + 1][0] = th[2]; bhi[ng * 2 + 1][1] = th[3];
                blo[ng * 2][0] = tl[0]; blo[ng * 2][1] = tl[1];
                blo[ng * 2 + 1][0] = tl[2]; blo[ng * 2 + 1][1] = tl[3];
            }
#pragma unroll
            for (int mh = 0; mh < 2; mh++)
#pragma unroll
                for (int nt = 0; nt < 8; nt++) {
                    mma_bf16(acc[mh][nt], ahi[mh], bhi[nt]);
                    mma_bf16(acc[mh][nt], alo[mh], bhi[nt]);
                    mma_bf16(acc[mh][nt], ahi[mh], blo[nt]);
                }
        }
    }

    // epilogue: bias + fp32 C + optional bf16 hi/lo decompose
#pragma unroll
    for (int mh = 0; mh < 2; mh++) {
        const int mrow = m0 + wm * 32 + mh * 16 + (lane >> 2);
#pragma unroll
        for (int nt = 0; nt < 8; nt++) {
            const int n = n0 + wn * 64 + nt * 8 + (lane & 3) * 2;
            const float2 bi = *(const float2*)&bias[n];
            const float v0 = acc[mh][nt][0] + bi.x;
            const float v1 = acc[mh][nt][1] + bi.y;
            const float v2 = acc[mh][nt][2] + bi.x;
            const float v3 = acc[mh][nt][3] + bi.y;
            const size_t o0 = (size_t)mrow * Cc + n;
            const size_t o1 = (size_t)(mrow + 8) * Cc + n;
            *(float2*)&C[o0] = make_float2(v0, v1);
            *(float2*)&C[o1] = make_float2(v2, v3);
            if (Ch) {
                const __nv_bfloat16 h0 = __float2bfloat16(v0);
                const __nv_bfloat16 h1 = __float2bfloat16(v1);
                const __nv_bfloat16 h2 = __float2bfloat16(v2);
                const __nv_bfloat16 h3 = __float2bfloat16(v3);
                *(__nv_bfloat162*)&Ch[o0] = __nv_bfloat162(h0, h1);
                *(__nv_bfloat162*)&Ch[o1] = __nv_bfloat162(h2, h3);
                *(__nv_bfloat162*)&Cl[o0] = __nv_bfloat162(
                    __float2bfloat16(v0 - __bfloat162float(h0)),
                    __float2bfloat16(v1 - __bfloat162float(h1)));
                *(__nv_bfloat162*)&Cl[o1] = __nv_bfloat162(
                    __float2bfloat16(v2 - __bfloat162float(h2)),
                    __float2bfloat16(v3 - __bfloat162float(h3)));
            }
        }
    }
}

// ---------------- conv implicit GEMM, 128x128 tile, reg-pipelined K32 (r5-proven) ----------
__global__ __launch_bounds__(256, 1)
void conv_mma_kernel(const __nv_bfloat16* __restrict__ a_hi,
                     const __nv_bfloat16* __restrict__ a_lo,
                     const __nv_bfloat16* __restrict__ b_hi,
                     const __nv_bfloat16* __restrict__ b_lo,
                     float* __restrict__ part)
{
    __shared__ char smem[32768];
    const uint32_t sb = smem_u32(smem);
    const uint32_t A_HI = sb, A_LO = sb + 8192, B_HI = sb + 16384, B_LO = sb + 24576;

    const int tid  = threadIdx.x;
    const int wid  = tid >> 5;
    const int lane = tid & 31;
    const int m0 = blockIdx.x * 128;
    const int n0 = blockIdx.y * 128;
    const int z  = blockIdx.z;
    const int cbeg = (z * NCHUNK) / 3;
    const int cend = ((z + 1) * NCHUNK) / 3;

    const int wm = wid & 3;
    const int wn = wid >> 2;

    int a_row[2], a_seg[2], a_h[2], a_w[2];
    long a_base[2];
    int b_rw[2], b_sg[2];
#pragma unroll
    for (int i = 0; i < 2; i++) {
        const int idx = tid + 256 * i;
        a_row[i] = idx >> 2;
        a_seg[i] = idx & 3;
        const int m = m0 + a_row[i];
        const int b = m / (Hh * Ww);
        a_h[i] = (m / Ww) % Hh;
        a_w[i] = m % Ww;
        a_base[i] = (long)b * Hh * Ww * Cc;
        b_rw[i] = idx >> 2;
        b_sg[i] = idx & 3;
    }

    float acc[2][8][4];
#pragma unroll
    for (int i = 0; i < 2; i++)
#pragma unroll
        for (int j = 0; j < 8; j++)
#pragma unroll
            for (int q = 0; q < 4; q++) acc[i][j][q] = 0.f;

    uint4 rAh[2], rAl[2], rBh[2], rBl[2];
    {
        const int kb = cbeg * 32;
        const int patch = kb >> 8;
        const int kh = patch / 5, kw = patch % 5;
        const int ci0 = kb & 255;
#pragma unroll
        for (int i = 0; i < 2; i++) {
            const int hh = a_h[i] + kh - 2;
            const int ww = a_w[i] + kw - 2;
            if (hh >= 0 && hh < Hh && ww >= 0 && ww < Ww) {
                const long off = a_base[i] + ((long)hh * Ww + ww) * Cc + ci0 + a_seg[i] * 8;
                rAh[i] = *(const uint4*)(a_hi + off);
                rAl[i] = *(const uint4*)(a_lo + off);
            } else {
                rAh[i] = make_uint4(0, 0, 0, 0);
                rAl[i] = make_uint4(0, 0, 0, 0);
            }
            const long boff = (long)(n0 + b_rw[i]) * KTOT + kb + b_sg[i] * 8;
            rBh[i] = *(const uint4*)(b_hi + boff);
            rBl[i] = *(const uint4*)(b_lo + boff);
        }
    }

    for (int c = cbeg; c < cend; c++) {
        __syncthreads();
#pragma unroll
        for (int i = 0; i < 2; i++) {
            const uint32_t soA = SWZ64((uint32_t)(a_row[i] * 64 + a_seg[i] * 16));
            *(uint4*)(smem + soA)        = rAh[i];
            *(uint4*)(smem + 8192 + soA) = rAl[i];
            const uint32_t soB = SWZ64((uint32_t)(b_rw[i] * 64 + b_sg[i] * 16));
            *(uint4*)(smem + 16384 + soB) = rBh[i];
            *(uint4*)(smem + 24576 + soB) = rBl[i];
        }
        __syncthreads();

        if (c + 1 < cend) {
            const int kb = (c + 1) * 32;
            const int patch = kb >> 8;
            const int kh = patch / 5, kw = patch % 5;
            const int ci0 = kb & 255;
#pragma unroll
            for (int i = 0; i < 2; i++) {
                const int hh = a_h[i] + kh - 2;
                const int ww = a_w[i] + kw - 2;
                if (hh >= 0 && hh < Hh && ww >= 0 && ww < Ww) {
                    const long off = a_base[i] + ((long)hh * Ww + ww) * Cc + ci0 + a_seg[i] * 8;
                    rAh[i] = *(const uint4*)(a_hi + off);
                    rAl[i] = *(const uint4*)(a_lo + off);
                } else {
                    rAh[i] = make_uint4(0, 0, 0, 0);
                    rAl[i] = make_uint4(0, 0, 0, 0);
                }
                const long boff = (long)(n0 + b_rw[i]) * KTOT + kb + b_sg[i] * 8;
                rBh[i] = *(const uint4*)(b_hi + boff);
                rBl[i] = *(const uint4*)(b_lo + boff);
            }
        }

#pragma unroll
        for (int kst = 0; kst < 2; kst++) {
            uint32_t ahi[2][4], alo[2][4];
#pragma unroll
            for (int mh = 0; mh < 2; mh++) {
                const int tile = lane >> 3;
                const int row = wm * 32 + mh * 16 + ((tile & 1) << 3) + (lane & 7);
                const int unit = kst * 2 + (tile >> 1);
                const uint32_t so = SWZ64((uint32_t)(row * 64 + unit * 16));
                ldsm4(ahi[mh], A_HI + so);
                ldsm4(alo[mh], A_LO + so);
            }
            uint32_t bhi[8][2], blo[8][2];
#pragma unroll
            for (int ng = 0; ng < 4; ng++) {
                const int tile = lane >> 3;
                const int row = wn * 64 + ng * 16 + ((tile >> 1) << 3) + (lane & 7);
                const int unit = kst * 2 + (tile & 1);
                const uint32_t so = SWZ64((uint32_t)(row * 64 + unit * 16));
                uint32_t th[4], tl[4];
                ldsm4(th, B_HI + so);
                ldsm4(tl, B_LO + so);
                bhi[ng * 2][0] = th[0]; bhi[ng * 2][1] = th[1];
                bhi[ng * 2 + 1][0] = th[2]; bhi[ng * 2 + 1][1] = th[3];
                blo[ng * 2][0] = tl[0]; blo[ng * 2][1] = tl[1];
                blo[ng * 2 + 1][0] = tl[2]; blo[ng * 2 + 1][1] = tl[3];
            }
#pragma unroll
            for (int mh = 0; mh < 2; mh++)
#pragma unroll
                for (int nt = 0; nt < 8; nt++) {
                    mma_bf16(acc[mh][nt], ahi[mh], bhi[nt]);
                    mma_bf16(acc[mh][nt], alo[mh], bhi[nt]);
                    mma_bf16(acc[mh][nt], ahi[mh], blo[nt]);
                }
        }
    }

    float* base = part + (size_t)z * NELEM;
#pragma unroll
    for (int mh = 0; mh < 2; mh++) {
        const int mrow = m0 + wm * 32 + mh * 16 + (lane >> 2);
#pragma unroll
        for (int nt = 0; nt < 8; nt++) {
            const int n = n0 + wn * 64 + nt * 8 + (lane & 3) * 2;
            *(float2*)&base[(size_t)mrow * Cc + n] =
                make_float2(acc[mh][nt][0], acc[mh][nt][1]);
            *(float2*)&base[(size_t)(mrow + 8) * Cc + n] =
                make_float2(acc[mh][nt][2], acc[mh][nt][3]);
        }
    }
}

// ---------------- decompose x into bf16 hi/lo ----------------
__global__ void decomp_x_kernel(const float* __restrict__ x,
                                __nv_bfloat16* __restrict__ hi, __nv_bfloat16* __restrict__ lo)
{
    const int i = blockIdx.x * blockDim.x + threadIdx.x;
    if (i < NELEM) {
        const float v = x[i];
        const __nv_bfloat16 h = __float2bfloat16(v);
        hi[i] = h;
        lo[i] = __float2bfloat16(v - __bfloat162float(h));
    }
}

// ---------------- decompose kvg = kp+vp into bf16 hi/lo ----------------
__global__ void decomp_kvg_kernel(const float* __restrict__ kp, const float* __restrict__ vp,
                                  __nv_bfloat16* __restrict__ hi, __nv_bfloat16* __restrict__ lo)
{
    const int i = blockIdx.x * blockDim.x + threadIdx.x;
    if (i < NELEM) {
        const float v = kp[i] + vp[i];
        const __nv_bfloat16 h = __float2bfloat16(v);
        hi[i] = h;
        lo[i] = __float2bfloat16(v - __bfloat162float(h));
    }
}

// ---------------- transpose + decompose conv weights: [6400,256] -> [256,6400] ----------------
__global__ void decomp_wt_kernel(const float* __restrict__ w,
                                 __nv_bfloat16* __restrict__ hi, __nv_bfloat16* __restrict__ lo)
{
    __shared__ float tile[32][33];
    const int k0 = blockIdx.x * 32;
    const int n0 = blockIdx.y * 32;
    const int tx = threadIdx.x, ty = threadIdx.y;
#pragma unroll
    for (int i = 0; i < 4; i++)
        tile[ty + i * 8][tx] = w[(long)(k0 + ty + i * 8) * Cc + n0 + tx];
    __syncthreads();
#pragma unroll
    for (int i = 0; i < 4; i++) {
        const float v = tile[tx][ty + i * 8];
        const __nv_bfloat16 h = __float2bfloat16(v);
        const long o = (long)(n0 + ty + i * 8) * KTOT + k0 + tx;
        hi[o] = h;
        lo[o] = __float2bfloat16(v - __bfloat162float(h));
    }
}

// ---------------- transpose + decompose 7 proj weights [256,256] -> [256,256]^T ----------------
struct W7 { const float* w[7]; };
__global__ void decomp_w7_kernel(W7 ws,
                                 __nv_bfloat16* __restrict__ hi, __nv_bfloat16* __restrict__ lo)
{
    __shared__ float tile[32][33];
    const int z  = blockIdx.z;
    const float* __restrict__ w = ws.w[z];
    const long zo = (long)z * Cc * Cc;
    const int k0 = blockIdx.x * 32;
    const int n0 = blockIdx.y * 32;
    const int tx = threadIdx.x, ty = threadIdx.y;
#pragma unroll
    for (int i = 0; i < 4; i++)
        tile[ty + i * 8][tx] = w[(long)(k0 + ty + i * 8) * Cc + n0 + tx];
    __syncthreads();
#pragma unroll
    for (int i = 0; i < 4; i++) {
        const float v = tile[tx][ty + i * 8];
        const __nv_bfloat16 h = __float2bfloat16(v);
        const long o = zo + (long)(n0 + ty + i * 8) * Cc + k0 + tx;
        hi[o] = h;
        lo[o] = __float2bfloat16(v - __bfloat162float(h));
    }
}

// ---------------- block mean pooling ----------------
__global__ void pool_kernel(const float* __restrict__ qp, const float* __restrict__ kp,
                            float* __restrict__ qloc, float* __restrict__ kloc)
{
    const int bp = blockIdx.x;
    const int c  = threadIdx.x;
    const float* qb = qp + (long)bp * LBLK * Cc + c;
    const float* kb = kp + (long)bp * LBLK * Cc + c;
    float sq = 0.f, sk = 0.f;
    for (int i = 0; i < LBLK; i++) { sq += qb[i * Cc]; sk += kb[i * Cc]; }
    qloc[bp * Cc + c] = sq * (1.f / (float)LBLK);
    kloc[bp * Cc + c] = sk * (1.f / (float)LBLK);
}

// ---------------- attention with inline routing (MUFU ex2, writes ctx hi/lo) ----------------
#define KCHUNK 128
__global__ void attention_kernel(const float* __restrict__ q2,
                                 const float* __restrict__ k2,
                                 const float* __restrict__ v2,
                                 const float* __restrict__ qloc,
                                 const float* __restrict__ kloc,
                                 __nv_bfloat16* __restrict__ ctx_hi,
                                 __nv_bfloat16* __restrict__ ctx_lo)
{
    __shared__ float Ks[KCHUNK * DK];
    __shared__ float Vs[KCHUNK * DK];
    __shared__ float Sl[8];
    __shared__ int   Rs[KV];

    const int blk = blockIdx.x;
    const int h = blk % NHh;
    const int p = (blk / NHh) % Pp;
    const int b = blk / (NHh * Pp);
    const int tid = threadIdx.x;
    const int wid = tid >> 5;
    const int lane = tid & 31;

    // inline routing: warp j computes qloc[bp] . kloc[b*8+j]; thread 0 top-4
    {
        const float* q = qloc + (b * Pp + p) * Cc;
        const float* k = kloc + (b * Pp + wid) * Cc;
        float partial = 0.f;
#pragma unroll
        for (int c = lane; c < Cc; c += 32) partial += q[c] * k[c];
#pragma unroll
        for (int o = 16; o; o >>= 1) partial += __shfl_xor_sync(0xffffffff, partial, o);
        if (lane == 0) Sl[wid] = partial;
        __syncthreads();
        if (tid == 0) {
            bool used[8] = {};
            for (int t = 0; t < KV; t++) {
                int best = 0; float bv = -1e30f;
                for (int j = 0; j < Pp; j++)
                    if (!used[j] && Sl[j] > bv) { bv = Sl[j]; best = j; }
                used[best] = true;
                Rs[t] = best;
            }
        }
        // Rs becomes visible at the first __syncthreads of the main loop
    }

    const bool active = (tid < LBLK);
    unsigned long long qv2[DK / 2], acc2[DK / 2];
    float m = -1e30f, l = 0.f;
    if (active) {
        const float* qrow = q2 + ((long)((b * Pp + p) * LBLK + tid)) * Cc + h * DK;
#pragma unroll
        for (int d2 = 0; d2 < DK / 2; d2++) {
            qv2[d2] = pk2(qrow[2 * d2] * QK_SCALE, qrow[2 * d2 + 1] * QK_SCALE);
            acc2[d2] = 0ull;
        }
    }

    for (int ch = 0; ch < LKEY / KCHUNK; ch++) {
        __syncthreads();
        const int kg0 = ch * KCHUNK;
        for (int i = tid; i < KCHUNK * (DK / 4); i += blockDim.x) {
            const int row = i >> 3;
            const int d4  = (i & 7) * 4;
            const int kg  = kg0 + row;
            const int ks  = kg / LBLK;
            const int rr  = kg - ks * LBLK;
            const int r   = Rs[ks];
            const long base = ((long)(b * Pp + r) * LBLK + rr) * Cc + h * DK + d4;
            *(float4*)&Ks[row * DK + d4] = *(const float4*)&k2[base];
            *(float4*)&Vs[row * DK + d4] = *(const float4*)&v2[base];
        }
        __syncthreads();
        if (active) {
            for (int k = 0; k < KCHUNK; k++) {
                const unsigned long long* kr = (const unsigned long long*)&Ks[k * DK];
                unsigned long long s0 = 0ull, s1 = 0ull, s2 = 0ull, s3 = 0ull;
#pragma unroll
                for (int d2 = 0; d2 < DK / 2; d2 += 4) {
                    s0 = ffma2(qv2[d2 + 0], kr[d2 + 0], s0);
                    s1 = ffma2(qv2[d2 + 1], kr[d2 + 1], s1);
                    s2 = ffma2(qv2[d2 + 2], kr[d2 + 2], s2);
                    s3 = ffma2(qv2[d2 + 3], kr[d2 + 3], s3);
                }
                const float2 f0 = upk2(s0), f1 = upk2(s1), f2 = upk2(s2), f3 = upk2(s3);
                const float s = ((f0.x + f0.y) + (f1.x + f1.y)) + ((f2.x + f2.y) + (f3.x + f3.y));
                const float mnew = fmaxf(m, s);
                const float corr = ex2f(m - mnew);
                const float pe   = ex2f(s - mnew);
                l = fmaf(l, corr, pe);
                const unsigned long long cc = pk2(corr, corr);
                const unsigned long long pp = pk2(pe, pe);
                const unsigned long long* vr = (const unsigned long long*)&Vs[k * DK];
#pragma unroll
                for (int d2 = 0; d2 < DK / 2; d2++)
                    acc2[d2] = ffma2(acc2[d2], cc, fmul2(pp, vr[d2]));
                m = mnew;
            }
        }
    }

    if (active) {
        const float inv = 1.0f / l;
        const long base = ((long)((b * Pp + p) * LBLK + tid)) * Cc + h * DK;
#pragma unroll
        for (int d2 = 0; d2 < DK / 2; d2++) {
            float2 f = upk2(acc2[d2]);
            const float v0 = f.x * inv, v1 = f.y * inv;
            const __nv_bfloat16 h0 = __float2bfloat16(v0);
            const __nv_bfloat16 h1 = __float2bfloat16(v1);
            *(__nv_bfloat162*)&ctx_hi[base + 2 * d2] = __nv_bfloat162(h0, h1);
            *(__nv_bfloat162*)&ctx_lo[base + 2 * d2] = __nv_bfloat162(
                __float2bfloat16(v0 - __bfloat162float(h0)),
                __float2bfloat16(v1 - __bfloat162float(h1)));
        }
    }
}

// ---------------- fused residual add + LayerNorm ----------------
__global__ void add_ln_kernel(const float* __restrict__ a, const float* __restrict__ bsrc,
                              const float* __restrict__ g, const float* __restrict__ beta,
                              float* __restrict__ out)
{
    const int mrow = blockIdx.x;
    const int c = threadIdx.x;
    __shared__ float red[Cc];
    const float v = a[(long)mrow * Cc + c] + bsrc[(long)mrow * Cc + c];
    red[c] = v;
    __syncthreads();
    for (int s = Cc / 2; s > 0; s >>= 1) {
        if (c < s) red[c] += red[c + s];
        __syncthreads();
    }
    const float mean = red[0] * (1.f / (float)Cc);
    __syncthreads();
    const float d = v - mean;
    red[c] = d * d;
    __syncthreads();
    for (int s = Cc / 2; s > 0; s >>= 1) {
        if (c < s) red[c] += red[c + s];
        __syncthreads();
    }
    const float var = red[0] * (1.f / (float)Cc);
    out[(long)mrow * Cc + c] = d * rsqrtf(var + 1e-5f) * g[c] + beta[c];
}

__global__ void add_lnK_kernel(const float* __restrict__ a, const float* __restrict__ pbase,
                               const float* __restrict__ cb,
                               const float* __restrict__ g, const float* __restrict__ beta,
                               float* __restrict__ out)
{
    const int mrow = blockIdx.x;
    const int c = threadIdx.x;
    __shared__ float red[Cc];
    const long off = (long)mrow * Cc + c;
    float v = a[off] + cb[c];
#pragma unroll
    for (int s = 0; s < NSPLIT; s++) v += pbase[off + (size_t)s * NELEM];
    red[c] = v;
    __syncthreads();
    for (int s = Cc / 2; s > 0; s >>= 1) {
        if (c < s) red[c] += red[c + s];
        __syncthreads();
    }
    const float mean = red[0] * (1.f / (float)Cc);
    __syncthreads();
    const float d = v - mean;
    red[c] = d * d;
    __syncthreads();
    for (int s = Cc / 2; s > 0; s >>= 1) {
        if (c < s) red[c] += red[c + s];
        __syncthreads();
    }
    const float var = red[0] * (1.f / (float)Cc);
    out[off] = d * rsqrtf(var + 1e-5f) * g[c] + beta[c];
}

// ---------------- launcher ----------------
extern "C" void kernel_launch(void* const* d_in, const int* in_sizes, int n_in,
                              void* d_out, int out_size)
{
    const float* x        = (const float*)d_in[0];
    const float* wq_proj  = (const float*)d_in[1];
    const float* bq_proj  = (const float*)d_in[2];
    const float* wk_proj  = (const float*)d_in[3];
    const float* bk_proj  = (const float*)d_in[4];
    const float* wv_proj  = (const float*)d_in[5];
    const float* bv_proj  = (const float*)d_in[6];
    const float* wq_a     = (const float*)d_in[7];
    const float* bq_a     = (const float*)d_in[8];
    const float* wk_a     = (const float*)d_in[9];
    const float* bk_a     = (const float*)d_in[10];
    const float* wv_a     = (const float*)d_in[11];
    const float* bv_a     = (const float*)d_in[12];
    const float* wo_a     = (const float*)d_in[13];
    const float* bo_a     = (const float*)d_in[14];
    const float* conv_w   = (const float*)d_in[15];
    const float* conv_b   = (const float*)d_in[16];
    const float* ln1_g    = (const float*)d_in[17];
    const float* ln1_b    = (const float*)d_in[18];
    const float* ln2_g    = (const float*)d_in[19];
    const float* ln2_b    = (const float*)d_in[20];
    float* out = (float*)d_out;

    float* buf = nullptr;   cudaGetSymbolAddress((void**)&buf, g_buf);
    float* loc = nullptr;   cudaGetSymbolAddress((void**)&loc, g_loc);
    __nv_bfloat16 *xh, *xl, *ah, *al, *cxh, *cxl, *kvh, *kvl, *wth, *wtl, *w7h, *w7l;
    cudaGetSymbolAddress((void**)&xh,  g_x_hi);
    cudaGetSymbolAddress((void**)&xl,  g_x_lo);
    cudaGetSymbolAddress((void**)&ah,  g_act_hi);
    cudaGetSymbolAddress((void**)&al,  g_act_lo);
    cudaGetSymbolAddress((void**)&cxh, g_ctx_hi);
    cudaGetSymbolAddress((void**)&cxl, g_ctx_lo);
    cudaGetSymbolAddress((void**)&kvh, g_kvg_hi);
    cudaGetSymbolAddress((void**)&kvl, g_kvg_lo);
    cudaGetSymbolAddress((void**)&wth, g_wt_hi);
    cudaGetSymbolAddress((void**)&wtl, g_wt_lo);
    cudaGetSymbolAddress((void**)&w7h, g_w7_hi);
    cudaGetSymbolAddress((void**)&w7l, g_w7_lo);

    float* qp   = buf + 0l * NELEM;
    float* kp   = buf + 1l * NELEM;
    float* vp   = buf + 2l * NELEM;
    float* xres = buf + 3l * NELEM;
    float* q2   = buf + 4l * NELEM;
    float* k2   = buf + 5l * NELEM;
    float* v2   = buf + 6l * NELEM;
    float* rout = buf + 7l * NELEM;
    float* cnvp = buf + 8l * NELEM;
    float* qloc = loc;
    float* kloc = loc + 16 * Cc;

    // 1: transpose+decompose 7 projection weights
    {
        W7 ws;
        ws.w[0] = wq_proj; ws.w[1] = wk_proj; ws.w[2] = wv_proj;
        ws.w[3] = wq_a;    ws.w[4] = wk_a;    ws.w[5] = wv_a;
        ws.w[6] = wo_a;
        decomp_w7_kernel<<<dim3(Cc / 32, Cc / 32, 7), dim3(32, 8)>>>(ws, w7h, w7l);
    }

    // 2: conv weight transpose+decompose
    decomp_wt_kernel<<<dim3(KTOT / 32, Cc / 32), dim3(32, 8)>>>(conv_w, wth, wtl);

    // 3: x decompose
    decomp_x_kernel<<<NELEM / 256, 256>>>(x, xh, xl);

    // 4: q/k/v block projections (tensor, profiled slot)
    {
        GemmSetT gs;
        for (int i = 0; i < 3; i++) {
            gs.Ah[i] = xh; gs.Al[i] = xl;
            gs.Bh[i] = w7h + i * WSZ; gs.Bl[i] = w7l + i * WSZ;
            gs.Ch[i] = ah + (long)i * NELEM; gs.Cl[i] = al + (long)i * NELEM;
        }
        gs.bias[0] = bq_proj; gs.bias[1] = bk_proj; gs.bias[2] = bv_proj;
        gs.C[0] = qp; gs.C[1] = kp; gs.C[2] = vp;
        gemm_mma_kernel<<<dim3(NROW / 128, Cc / 128, 3), 256>>>(gs);
    }

    // 5: conv input decompose (k_p + v_p)
    decomp_kvg_kernel<<<NELEM / 256, 256>>>(kp, vp, kvh, kvl);

    // 6: conv via reg-pipelined mma.sync
    conv_mma_kernel<<<dim3(NROW / 128, Cc / 128, NSPLIT), 256>>>(kvh, kvl, wth, wtl, cnvp);

    // 7: pooling
    pool_kernel<<<Bsz * Pp, Cc>>>(qp, kp, qloc, kloc);

    // 8: attention head projections (tensor)
    {
        GemmSetT gs;
        for (int i = 0; i < 3; i++) {
            gs.Ah[i] = ah + (long)i * NELEM; gs.Al[i] = al + (long)i * NELEM;
            gs.Bh[i] = w7h + (3 + i) * WSZ;  gs.Bl[i] = w7l + (3 + i) * WSZ;
            gs.Ch[i] = nullptr; gs.Cl[i] = nullptr;
        }
        gs.bias[0] = bq_a; gs.bias[1] = bk_a; gs.bias[2] = bv_a;
        gs.C[0] = q2; gs.C[1] = k2; gs.C[2] = v2;
        gemm_mma_kernel<<<dim3(NROW / 128, Cc / 128, 3), 256>>>(gs);
    }

    // 9: routed attention (routing inline; emits ctx hi/lo)
    attention_kernel<<<Bsz * Pp * NHh, 256>>>(q2, k2, v2, qloc, kloc, cxh, cxl);

    // 10: output projection (tensor, single matrix)
    {
        GemmSetT gs;
        gs.Ah[0] = cxh; gs.Al[0] = cxl;
        gs.Bh[0] = w7h + 6 * WSZ; gs.Bl[0] = w7l + 6 * WSZ;
        gs.bias[0] = bo_a;
        gs.C[0] = rout;
        gs.Ch[0] = nullptr; gs.Cl[0] = nullptr;
        for (int i = 1; i < 3; i++) {
            gs.Ah[i] = cxh; gs.Al[i] = cxl;
            gs.Bh[i] = w7h; gs.Bl[i] = w7l;
            gs.bias[i] = bo_a; gs.C[i] = rout;
            gs.Ch[i] = nullptr; gs.Cl[i] = nullptr;
        }
        gemm_mma_kernel<<<dim3(NROW / 128, Cc / 128, 1), 256>>>(gs);
    }

    // 11-12: LayerNorms
    add_ln_kernel<<<NROW, Cc>>>(x, rout, ln1_g, ln1_b, xres);
    add_lnK_kernel<<<NROW, Cc>>>(xres, cnvp, conv_b, ln2_g, ln2_b, out);
}